// round 1
// baseline (speedup 1.0000x reference)
#include <cuda_runtime.h>
#include <cuda_bf16.h>
#include <math.h>

// Problem constants
#define BB 2
#define SS 2048
#define DM 1024
#define NH 16
#define DH 64
#define DFF 2752
#define MM (BB*SS)          // 4096 rows
#define EPSV 1e-5f

// ---------------- scratch (static __device__, no allocation) ----------------
__device__ float g_xn  [MM*DM];
__device__ float g_q   [MM*DM];
__device__ float g_k   [MM*DM];
__device__ float g_v   [MM*DM];
__device__ float g_attn[MM*DM];
__device__ float g_hres[MM*DM];
__device__ float g_hn  [MM*DM];
__device__ float g_f1  [MM*DFF];
__device__ float g_f3  [MM*DFF];

// ---------------- RMSNorm: one block per row (D=1024, 256 thr x4) ----------
__global__ __launch_bounds__(256) void rmsnorm_k(const float* __restrict__ x,
                                                 const float* __restrict__ g,
                                                 float* __restrict__ out) {
    int row = blockIdx.x;
    const float* xr = x + (size_t)row * DM;
    float* orow = out + (size_t)row * DM;
    int t = threadIdx.x;
    float4 v = *(const float4*)&xr[t * 4];
    float ss = v.x*v.x + v.y*v.y + v.z*v.z + v.w*v.w;
    // warp reduce
    for (int o = 16; o > 0; o >>= 1) ss += __shfl_xor_sync(0xffffffffu, ss, o);
    __shared__ float wsum[8];
    if ((t & 31) == 0) wsum[t >> 5] = ss;
    __syncthreads();
    if (t < 8) {
        float s = wsum[t];
        for (int o = 4; o > 0; o >>= 1) s += __shfl_xor_sync(0xffu, s, o);
        if (t == 0) wsum[0] = s;
    }
    __syncthreads();
    float inv = rsqrtf(wsum[0] * (1.0f / DM) + EPSV);
    float4 gv = *(const float4*)&g[t * 4];
    float4 ov;
    ov.x = v.x * inv * gv.x; ov.y = v.y * inv * gv.y;
    ov.z = v.z * inv * gv.z; ov.w = v.w * inv * gv.w;
    *(float4*)&orow[t * 4] = ov;
}

// ---------------- Tiled fp32 GEMM: C[M,N] = A[M,K] @ W[K,N] -----------------
// EPI: 0 = plain, 1 = C = extra + AB (residual), 2 = C = silu(AB),
//      3 = C = extra * AB (elementwise gate)
// Requires M%64==0, N%64==0, K%16==0 (all shapes here satisfy this).
template <int EPI>
__global__ __launch_bounds__(256) void gemm_k(const float* __restrict__ A,
                                              const float* __restrict__ W,
                                              const float* __restrict__ extra,
                                              float* __restrict__ C,
                                              int M_, int N_, int K_) {
    const int BM = 64, BN = 64, BK = 16;
    __shared__ float As[BK][BM + 1];   // +1 pad: conflict-free transposed store
    __shared__ float Bs[BK][BN];
    int bm = blockIdx.y * BM, bn = blockIdx.x * BN;
    int tid = threadIdx.x;
    int tx = tid & 15, ty = tid >> 4;
    float acc[4][4] = {};
    for (int k0 = 0; k0 < K_; k0 += BK) {
        #pragma unroll
        for (int i = 0; i < 4; i++) {       // A tile 64x16 -> As[k][m]
            int e = tid + i * 256;
            int c = e & 15, r = e >> 4;
            As[c][r] = A[(size_t)(bm + r) * K_ + k0 + c];
        }
        #pragma unroll
        for (int i = 0; i < 4; i++) {       // W tile 16x64 -> Bs[k][n]
            int e = tid + i * 256;
            int r = e >> 6, c = e & 63;
            Bs[r][c] = W[(size_t)(k0 + r) * N_ + bn + c];
        }
        __syncthreads();
        #pragma unroll
        for (int kk = 0; kk < BK; kk++) {
            float a0 = As[kk][ty*4+0], a1 = As[kk][ty*4+1];
            float a2 = As[kk][ty*4+2], a3 = As[kk][ty*4+3];
            float4 bv = *(const float4*)&Bs[kk][tx * 4];
            acc[0][0] += a0*bv.x; acc[0][1] += a0*bv.y; acc[0][2] += a0*bv.z; acc[0][3] += a0*bv.w;
            acc[1][0] += a1*bv.x; acc[1][1] += a1*bv.y; acc[1][2] += a1*bv.z; acc[1][3] += a1*bv.w;
            acc[2][0] += a2*bv.x; acc[2][1] += a2*bv.y; acc[2][2] += a2*bv.z; acc[2][3] += a2*bv.w;
            acc[3][0] += a3*bv.x; acc[3][1] += a3*bv.y; acc[3][2] += a3*bv.z; acc[3][3] += a3*bv.w;
        }
        __syncthreads();
    }
    #pragma unroll
    for (int i = 0; i < 4; i++) {
        int row = bm + ty * 4 + i;
        #pragma unroll
        for (int j = 0; j < 4; j++) {
            int col = bn + tx * 4 + j;
            size_t idx = (size_t)row * N_ + col;
            float vacc = acc[i][j];
            if (EPI == 0)      C[idx] = vacc;
            else if (EPI == 1) C[idx] = extra[idx] + vacc;
            else if (EPI == 2) C[idx] = vacc / (1.0f + expf(-vacc));   // silu
            else               C[idx] = extra[idx] * vacc;             // gate mul
        }
    }
}

// ---------------- Flash attention (causal), 64x64 tiles ---------------------
// grid: (S/64, H, B), block: 128 threads. q/k/v/o layout: [b, s, h*DH + d]
#define ROWP 68   // padded row stride (floats) for 64-wide tiles
__global__ __launch_bounds__(128) void attn_k(const float* __restrict__ q,
                                              const float* __restrict__ k,
                                              const float* __restrict__ v,
                                              float* __restrict__ o) {
    extern __shared__ float sm[];
    float* Qs = sm;                  // 64*ROWP
    float* Ks = Qs + 64 * ROWP;
    float* Vs = Ks + 64 * ROWP;
    float* Ss = Vs + 64 * ROWP;
    float* Lrow = Ss + 64 * ROWP;    // 64
    float* Mrow = Lrow + 64;         // 64
    float* Rs = Mrow + 64;           // 64

    int qt = blockIdx.x, h = blockIdx.y, b = blockIdx.z;
    int tid = threadIdx.x;
    const float scale = 0.125f;      // 1/sqrt(64)

    const size_t bh = (size_t)b * SS * DM + h * DH;
    const float* qb = q + bh;
    const float* kb = k + bh;
    const float* vb = v + bh;

    // load Q tile (64 rows x 64 dims), float4 coalesced
    #pragma unroll
    for (int i = 0; i < 8; i++) {
        int e4 = tid + i * 128;          // 1024 float4s
        int r = e4 >> 4, d4 = (e4 & 15) * 4;
        float4 val = *(const float4*)&qb[(size_t)(qt * 64 + r) * DM + d4];
        *(float4*)&Qs[r * ROWP + d4] = val;
    }
    if (tid < 64) { Mrow[tid] = -1e30f; Lrow[tid] = 0.0f; }

    int r = tid & 63;
    int co = (tid >> 6) * 32;
    float acc[32];
    #pragma unroll
    for (int c = 0; c < 32; c++) acc[c] = 0.0f;

    for (int kt = 0; kt <= qt; kt++) {
        // load K, V tiles
        #pragma unroll
        for (int i = 0; i < 8; i++) {
            int e4 = tid + i * 128;
            int rr = e4 >> 4, d4 = (e4 & 15) * 4;
            size_t gidx = (size_t)(kt * 64 + rr) * DM + d4;
            *(float4*)&Ks[rr * ROWP + d4] = *(const float4*)&kb[gidx];
            *(float4*)&Vs[rr * ROWP + d4] = *(const float4*)&vb[gidx];
        }
        __syncthreads();

        // Stage A: S = scale * Q K^T (each thread: row r, 32 cols)
        int j0 = (tid >> 6) * 32;
        for (int j = j0; j < j0 + 32; j++) {
            float s = 0.0f;
            #pragma unroll
            for (int d4 = 0; d4 < 64; d4 += 4) {
                float4 qv = *(const float4*)&Qs[r * ROWP + d4];
                float4 kv = *(const float4*)&Ks[j * ROWP + d4];
                s += qv.x*kv.x + qv.y*kv.y + qv.z*kv.z + qv.w*kv.w;
            }
            s *= scale;
            if (kt == qt && j > r) s = -1e30f;
            Ss[r * ROWP + j] = s;
        }
        __syncthreads();

        // Stage B: online softmax per row (threads 0..63)
        if (tid < 64) {
            int rr = tid;
            float m_old = Mrow[rr];
            float mx = m_old;
            #pragma unroll
            for (int j = 0; j < 64; j++) mx = fmaxf(mx, Ss[rr * ROWP + j]);
            float rsc = __expf(m_old - mx);
            float sum = 0.0f;
            #pragma unroll
            for (int j = 0; j < 64; j++) {
                float p = __expf(Ss[rr * ROWP + j] - mx);
                Ss[rr * ROWP + j] = p;
                sum += p;
            }
            Lrow[rr] = Lrow[rr] * rsc + sum;
            Mrow[rr] = mx;
            Rs[rr] = rsc;
        }
        __syncthreads();

        // Stage C: rescale + P @ V (each thread: row r, dims co..co+31)
        float rsc = Rs[r];
        #pragma unroll
        for (int c = 0; c < 32; c++) acc[c] *= rsc;
        for (int j = 0; j < 64; j++) {
            float p = Ss[r * ROWP + j];
            #pragma unroll
            for (int c4 = 0; c4 < 32; c4 += 4) {
                float4 vv = *(const float4*)&Vs[j * ROWP + co + c4];
                acc[c4+0] += p * vv.x; acc[c4+1] += p * vv.y;
                acc[c4+2] += p * vv.z; acc[c4+3] += p * vv.w;
            }
        }
        __syncthreads();   // protect Ks/Vs/Ss before next tile load
    }

    float linv = 1.0f / Lrow[r];
    float* ob = o + bh + (size_t)(qt * 64 + r) * DM + co;
    #pragma unroll
    for (int c4 = 0; c4 < 32; c4 += 4) {
        float4 ov;
        ov.x = acc[c4+0]*linv; ov.y = acc[c4+1]*linv;
        ov.z = acc[c4+2]*linv; ov.w = acc[c4+3]*linv;
        *(float4*)&ob[c4] = ov;
    }
}

// ---------------- launch ----------------------------------------------------
extern "C" void kernel_launch(void* const* d_in, const int* in_sizes, int n_in,
                              void* d_out, int out_size) {
    const float* x   = (const float*)d_in[0];
    const float* g1  = (const float*)d_in[1];
    const float* g2  = (const float*)d_in[2];
    const float* w_q = (const float*)d_in[3];
    const float* w_k = (const float*)d_in[4];
    const float* w_v = (const float*)d_in[5];
    const float* w_o = (const float*)d_in[6];
    const float* w1  = (const float*)d_in[7];
    const float* w2  = (const float*)d_in[8];
    const float* w3  = (const float*)d_in[9];
    float* out = (float*)d_out;

    float *xn, *qp, *kp, *vp, *ap, *hres, *hn, *f1, *f3;
    cudaGetSymbolAddress((void**)&xn,   g_xn);
    cudaGetSymbolAddress((void**)&qp,   g_q);
    cudaGetSymbolAddress((void**)&kp,   g_k);
    cudaGetSymbolAddress((void**)&vp,   g_v);
    cudaGetSymbolAddress((void**)&ap,   g_attn);
    cudaGetSymbolAddress((void**)&hres, g_hres);
    cudaGetSymbolAddress((void**)&hn,   g_hn);
    cudaGetSymbolAddress((void**)&f1,   g_f1);
    cudaGetSymbolAddress((void**)&f3,   g_f3);

    int attn_smem = (4 * 64 * ROWP + 3 * 64) * sizeof(float);   // ~70 KB
    cudaFuncSetAttribute(attn_k, cudaFuncAttributeMaxDynamicSharedMemorySize, attn_smem);

    dim3 gD(DM / 64, MM / 64);      // (16, 64)
    dim3 gF(DFF / 64, MM / 64);     // (43, 64)

    // 1. norm1
    rmsnorm_k<<<MM, 256>>>(x, g1, xn);
    // 2. q, k, v projections
    gemm_k<0><<<gD, 256>>>(xn, w_q, nullptr, qp, MM, DM, DM);
    gemm_k<0><<<gD, 256>>>(xn, w_k, nullptr, kp, MM, DM, DM);
    gemm_k<0><<<gD, 256>>>(xn, w_v, nullptr, vp, MM, DM, DM);
    // 3. causal flash attention
    attn_k<<<dim3(SS / 64, NH, BB), 128, attn_smem>>>(qp, kp, vp, ap);
    // 4. h_res = x + attn @ w_o
    gemm_k<1><<<gD, 256>>>(ap, w_o, x, hres, MM, DM, DM);
    // 5. norm2
    rmsnorm_k<<<MM, 256>>>(hres, g2, hn);
    // 6. f1 = silu(hn @ w1)
    gemm_k<2><<<gF, 256>>>(hn, w1, nullptr, f1, MM, DFF, DM);
    // 7. f3 = f1 * (hn @ w3)
    gemm_k<3><<<gF, 256>>>(hn, w3, f1, f3, MM, DFF, DM);
    // 8. out = h_res + f3 @ w2
    gemm_k<1><<<gD, 256>>>(f3, w2, hres, out, MM, DM, DFF);
}

// round 3
// speedup vs baseline: 2.2565x; 2.2565x over previous
#include <cuda_runtime.h>
#include <cuda_bf16.h>
#include <math.h>
#include <stdint.h>

// Problem constants
#define BB 2
#define SS 2048
#define DM 1024
#define NH 16
#define DH 64
#define DFF 2752
#define MM (BB*SS)          // 4096 rows
#define EPSV 1e-5f

// ---------------- scratch (static __device__, no allocation) ----------------
__device__ float g_xn  [MM*DM];
__device__ float g_q   [MM*DM];
__device__ float g_k   [MM*DM];
__device__ float g_v   [MM*DM];
__device__ float g_attn[MM*DM];
__device__ float g_hres[MM*DM];
__device__ float g_hn  [MM*DM];
__device__ float g_f1  [MM*DFF];
__device__ float g_f3  [MM*DFF];
// transposed (tf32-rounded) weights, [N,K] row-major
__device__ float g_wqT[DM*DM];
__device__ float g_wkT[DM*DM];
__device__ float g_wvT[DM*DM];
__device__ float g_woT[DM*DM];
__device__ float g_w1T[DFF*DM];
__device__ float g_w3T[DFF*DM];
__device__ float g_w2T[DM*DFF];

// ---------------- helpers ----------------------------------------------------
__device__ __forceinline__ uint32_t s2u(const void* p) {
    uint32_t a;
    asm("{ .reg .u64 t; cvta.to.shared.u64 t, %1; cvt.u32.u64 %0, t; }"
        : "=r"(a) : "l"(p));
    return a;
}
__device__ __forceinline__ void cpa16(uint32_t dst, const void* src, uint32_t bytes) {
    asm volatile("cp.async.cg.shared.global [%0], [%1], 16, %2;"
                 :: "r"(dst), "l"(src), "r"(bytes) : "memory");
}
__device__ __forceinline__ void mma_tf32(float* c, const uint32_t* a, const uint32_t* b) {
    asm volatile("mma.sync.aligned.m16n8k8.row.col.f32.tf32.tf32.f32 "
        "{%0,%1,%2,%3}, {%4,%5,%6,%7}, {%8,%9}, {%0,%1,%2,%3};"
        : "+f"(c[0]), "+f"(c[1]), "+f"(c[2]), "+f"(c[3])
        : "r"(a[0]), "r"(a[1]), "r"(a[2]), "r"(a[3]), "r"(b[0]), "r"(b[1]));
}

// ---------------- RMSNorm ----------------------------------------------------
__global__ __launch_bounds__(256) void rmsnorm_k(const float* __restrict__ x,
                                                 const float* __restrict__ g,
                                                 float* __restrict__ out) {
    int row = blockIdx.x;
    const float* xr = x + (size_t)row * DM;
    float* orow = out + (size_t)row * DM;
    int t = threadIdx.x;
    float4 v = *(const float4*)&xr[t * 4];
    float ss = v.x*v.x + v.y*v.y + v.z*v.z + v.w*v.w;
    for (int o = 16; o > 0; o >>= 1) ss += __shfl_xor_sync(0xffffffffu, ss, o);
    __shared__ float wsum[8];
    if ((t & 31) == 0) wsum[t >> 5] = ss;
    __syncthreads();
    if (t < 8) {
        float s = wsum[t];
        for (int o = 4; o > 0; o >>= 1) s += __shfl_xor_sync(0xffu, s, o);
        if (t == 0) wsum[0] = s;
    }
    __syncthreads();
    float inv = rsqrtf(wsum[0] * (1.0f / DM) + EPSV);
    float4 gv = *(const float4*)&g[t * 4];
    float4 ov;
    ov.x = v.x * inv * gv.x; ov.y = v.y * inv * gv.y;
    ov.z = v.z * inv * gv.z; ov.w = v.w * inv * gv.w;
    *(float4*)&orow[t * 4] = ov;
}

// ---------------- Weight transpose (+ tf32 RN rounding) ---------------------
__global__ __launch_bounds__(256) void transpose_k(const float* __restrict__ in,
                                                   float* __restrict__ out,
                                                   int R, int C) {
    __shared__ float t[32][33];
    int bx = blockIdx.x * 32, by = blockIdx.y * 32;
    int tx = threadIdx.x, ty = threadIdx.y;
    #pragma unroll
    for (int i = 0; i < 32; i += 8) {
        float v = in[(size_t)(by + ty + i) * C + bx + tx];
        asm("cvt.rna.tf32.f32 %0, %0;" : "+f"(v));
        t[ty + i][tx] = v;
    }
    __syncthreads();
    #pragma unroll
    for (int i = 0; i < 32; i += 8)
        out[(size_t)(bx + ty + i) * R + by + tx] = t[tx][ty + i];
}

// ---------------- tf32 mma.sync GEMM -----------------------------------------
// C[M,N] = A[M,K] @ Wt[N,K]^T.   BM=BN=128, BK=32, 3-stage cp.async pipeline.
// 8 warps as 4(M) x 2(N); warp tile 32x64 = 2x8 m16n8k8 tiles.
// EPI: 0 plain, 1 residual(+extra), 2 silu, 3 gate(*extra)
#define BKP 36                      // padded K stride (floats)
#define STG_F (128*BKP)             // floats per operand per stage (4608)
#define STG_B (STG_F*4)             // 18432 bytes
#define STAGE_BYTES (2u*STG_B)      // A + B
#define NSTAGE 3
#define GSMEM (NSTAGE*STAGE_BYTES)  // 110592

template <int EPI>
__global__ __launch_bounds__(256) void gemm_mma(
    const float* __restrict__ A, const float* __restrict__ Bw,
    const float* __restrict__ extra, float* __restrict__ C,
    int M_, int N_, int K_)
{
    extern __shared__ float smf[];
    uint32_t smb = s2u(smf);
    int tid = threadIdx.x, lane = tid & 31, wid = tid >> 5;
    int wm = wid & 3, wn = wid >> 2;       // 4 x 2 warp grid
    int g = lane >> 2, tg = lane & 3;      // mma group / thread-in-group
    int bm = blockIdx.y * 128, bn = blockIdx.x * 128;
    int nt = K_ >> 5;                       // BK=32 tiles

    float acc[2][8][4];
    #pragma unroll
    for (int i = 0; i < 2; i++)
        #pragma unroll
        for (int j = 0; j < 8; j++)
            #pragma unroll
            for (int c = 0; c < 4; c++) acc[i][j][c] = 0.0f;

    // stage loader: 4 x 16B per thread per operand
    auto load_stage = [&](int s, int t) {
        int k0 = t * 32;
        uint32_t sa = smb + s * STAGE_BYTES;
        uint32_t sbb = sa + STG_B;
        #pragma unroll
        for (int i = 0; i < 4; i++) {
            int e = tid + i * 256;
            int row = e >> 3, ch = e & 7;
            // A rows always valid (M,K multiples of 128/32)
            cpa16(sa + row * (BKP*4) + ch * 16,
                  A + (size_t)(bm + row) * K_ + k0 + ch * 4, 16u);
            int brow = bn + row;
            const float* bs = Bw + (size_t)(brow < N_ ? brow : 0) * K_ + k0 + ch * 4;
            cpa16(sbb + row * (BKP*4) + ch * 16, bs, brow < N_ ? 16u : 0u);
        }
    };

    // prologue: stages 0,1
    load_stage(0, 0);
    asm volatile("cp.async.commit_group;");
    if (nt > 1) load_stage(1, 1);
    asm volatile("cp.async.commit_group;");

    for (int t = 0; t < nt; t++) {
        if (t + 2 < nt) load_stage((t + 2) % NSTAGE, t + 2);
        asm volatile("cp.async.commit_group;");
        asm volatile("cp.async.wait_group 2;");
        __syncthreads();

        const float* As = smf + (t % NSTAGE) * (STAGE_BYTES/4);
        const float* Bs = As + STG_F;
        #pragma unroll
        for (int ks = 0; ks < 4; ks++) {
            int kb = ks * 8;
            uint32_t af[2][4], bf[8][2];
            #pragma unroll
            for (int mt = 0; mt < 2; mt++) {
                int rb = wm * 32 + mt * 16;
                af[mt][0] = __float_as_uint(As[(rb + g    ) * BKP + kb + tg    ]);
                af[mt][1] = __float_as_uint(As[(rb + g + 8) * BKP + kb + tg    ]);
                af[mt][2] = __float_as_uint(As[(rb + g    ) * BKP + kb + tg + 4]);
                af[mt][3] = __float_as_uint(As[(rb + g + 8) * BKP + kb + tg + 4]);
            }
            #pragma unroll
            for (int ntile = 0; ntile < 8; ntile++) {
                int nb = wn * 64 + ntile * 8;
                bf[ntile][0] = __float_as_uint(Bs[(nb + g) * BKP + kb + tg    ]);
                bf[ntile][1] = __float_as_uint(Bs[(nb + g) * BKP + kb + tg + 4]);
            }
            #pragma unroll
            for (int mt = 0; mt < 2; mt++)
                #pragma unroll
                for (int ntile = 0; ntile < 8; ntile++)
                    mma_tf32(acc[mt][ntile], af[mt], bf[ntile]);
        }
        __syncthreads();
    }

    // epilogue
    #pragma unroll
    for (int mt = 0; mt < 2; mt++) {
        int rr0 = bm + wm * 32 + mt * 16 + g;
        #pragma unroll
        for (int ntile = 0; ntile < 8; ntile++) {
            int cc = bn + wn * 64 + ntile * 8 + 2 * tg;
            if (cc >= N_) continue;
            #pragma unroll
            for (int half = 0; half < 2; half++) {
                int rr = rr0 + half * 8;
                float v0 = acc[mt][ntile][half * 2 + 0];
                float v1 = acc[mt][ntile][half * 2 + 1];
                size_t idx = (size_t)rr * N_ + cc;
                float2 o;
                if (EPI == 0) {
                    o = make_float2(v0, v1);
                } else if (EPI == 1) {
                    float2 e = *(const float2*)&extra[idx];
                    o = make_float2(e.x + v0, e.y + v1);
                } else if (EPI == 2) {
                    o.x = v0 / (1.0f + __expf(-v0));
                    o.y = v1 / (1.0f + __expf(-v1));
                } else {
                    float2 e = *(const float2*)&extra[idx];
                    o = make_float2(e.x * v0, e.y * v1);
                }
                *(float2*)&C[idx] = o;
            }
        }
    }
}

// ---------------- Flash attention (causal), 64x64 tiles ---------------------
#define ROWP 68
__global__ __launch_bounds__(128) void attn_k(const float* __restrict__ q,
                                              const float* __restrict__ k,
                                              const float* __restrict__ v,
                                              float* __restrict__ o) {
    extern __shared__ float sm[];
    float* Qs = sm;
    float* Ks = Qs + 64 * ROWP;
    float* Vs = Ks + 64 * ROWP;
    float* Ss = Vs + 64 * ROWP;
    float* Lrow = Ss + 64 * ROWP;
    float* Mrow = Lrow + 64;
    float* Rs = Mrow + 64;

    int qt = blockIdx.x, h = blockIdx.y, b = blockIdx.z;
    int tid = threadIdx.x;
    const float scale = 0.125f;

    const size_t bh = (size_t)b * SS * DM + h * DH;
    const float* qb = q + bh;
    const float* kb = k + bh;
    const float* vb = v + bh;

    #pragma unroll
    for (int i = 0; i < 8; i++) {
        int e4 = tid + i * 128;
        int r = e4 >> 4, d4 = (e4 & 15) * 4;
        float4 val = *(const float4*)&qb[(size_t)(qt * 64 + r) * DM + d4];
        *(float4*)&Qs[r * ROWP + d4] = val;
    }
    if (tid < 64) { Mrow[tid] = -1e30f; Lrow[tid] = 0.0f; }

    int r = tid & 63;
    int co = (tid >> 6) * 32;
    float acc[32];
    #pragma unroll
    for (int c = 0; c < 32; c++) acc[c] = 0.0f;

    for (int kt = 0; kt <= qt; kt++) {
        #pragma unroll
        for (int i = 0; i < 8; i++) {
            int e4 = tid + i * 128;
            int rr = e4 >> 4, d4 = (e4 & 15) * 4;
            size_t gidx = (size_t)(kt * 64 + rr) * DM + d4;
            *(float4*)&Ks[rr * ROWP + d4] = *(const float4*)&kb[gidx];
            *(float4*)&Vs[rr * ROWP + d4] = *(const float4*)&vb[gidx];
        }
        __syncthreads();

        int j0 = (tid >> 6) * 32;
        for (int j = j0; j < j0 + 32; j++) {
            float s = 0.0f;
            #pragma unroll
            for (int d4 = 0; d4 < 64; d4 += 4) {
                float4 qv = *(const float4*)&Qs[r * ROWP + d4];
                float4 kv = *(const float4*)&Ks[j * ROWP + d4];
                s += qv.x*kv.x + qv.y*kv.y + qv.z*kv.z + qv.w*kv.w;
            }
            s *= scale;
            if (kt == qt && j > r) s = -1e30f;
            Ss[r * ROWP + j] = s;
        }
        __syncthreads();

        if (tid < 64) {
            int rr = tid;
            float m_old = Mrow[rr];
            float mx = m_old;
            #pragma unroll
            for (int j = 0; j < 64; j++) mx = fmaxf(mx, Ss[rr * ROWP + j]);
            float rsc = __expf(m_old - mx);
            float sum = 0.0f;
            #pragma unroll
            for (int j = 0; j < 64; j++) {
                float p = __expf(Ss[rr * ROWP + j] - mx);
                Ss[rr * ROWP + j] = p;
                sum += p;
            }
            Lrow[rr] = Lrow[rr] * rsc + sum;
            Mrow[rr] = mx;
            Rs[rr] = rsc;
        }
        __syncthreads();

        float rsc = Rs[r];
        #pragma unroll
        for (int c = 0; c < 32; c++) acc[c] *= rsc;
        for (int j = 0; j < 64; j++) {
            float p = Ss[r * ROWP + j];
            #pragma unroll
            for (int c4 = 0; c4 < 32; c4 += 4) {
                float4 vv = *(const float4*)&Vs[j * ROWP + co + c4];
                acc[c4+0] += p * vv.x; acc[c4+1] += p * vv.y;
                acc[c4+2] += p * vv.z; acc[c4+3] += p * vv.w;
            }
        }
        __syncthreads();
    }

    float linv = 1.0f / Lrow[r];
    float* ob = o + bh + (size_t)(qt * 64 + r) * DM + co;
    #pragma unroll
    for (int c4 = 0; c4 < 32; c4 += 4) {
        float4 ov;
        ov.x = acc[c4+0]*linv; ov.y = acc[c4+1]*linv;
        ov.z = acc[c4+2]*linv; ov.w = acc[c4+3]*linv;
        *(float4*)&ob[c4] = ov;
    }
}

// ---------------- launch ------------------------------------------------------
extern "C" void kernel_launch(void* const* d_in, const int* in_sizes, int n_in,
                              void* d_out, int out_size) {
    const float* x   = (const float*)d_in[0];
    const float* g1  = (const float*)d_in[1];
    const float* g2  = (const float*)d_in[2];
    const float* w_q = (const float*)d_in[3];
    const float* w_k = (const float*)d_in[4];
    const float* w_v = (const float*)d_in[5];
    const float* w_o = (const float*)d_in[6];
    const float* w1  = (const float*)d_in[7];
    const float* w2  = (const float*)d_in[8];
    const float* w3  = (const float*)d_in[9];
    float* out = (float*)d_out;

    float *xn, *qp, *kp, *vp, *ap, *hres, *hn, *f1, *f3;
    float *wqT, *wkT, *wvT, *woT, *w1T, *w3T, *w2T;
    cudaGetSymbolAddress((void**)&xn,   g_xn);
    cudaGetSymbolAddress((void**)&qp,   g_q);
    cudaGetSymbolAddress((void**)&kp,   g_k);
    cudaGetSymbolAddress((void**)&vp,   g_v);
    cudaGetSymbolAddress((void**)&ap,   g_attn);
    cudaGetSymbolAddress((void**)&hres, g_hres);
    cudaGetSymbolAddress((void**)&hn,   g_hn);
    cudaGetSymbolAddress((void**)&f1,   g_f1);
    cudaGetSymbolAddress((void**)&f3,   g_f3);
    cudaGetSymbolAddress((void**)&wqT,  g_wqT);
    cudaGetSymbolAddress((void**)&wkT,  g_wkT);
    cudaGetSymbolAddress((void**)&wvT,  g_wvT);
    cudaGetSymbolAddress((void**)&woT,  g_woT);
    cudaGetSymbolAddress((void**)&w1T,  g_w1T);
    cudaGetSymbolAddress((void**)&w3T,  g_w3T);
    cudaGetSymbolAddress((void**)&w2T,  g_w2T);

    cudaFuncSetAttribute(gemm_mma<0>, cudaFuncAttributeMaxDynamicSharedMemorySize, GSMEM);
    cudaFuncSetAttribute(gemm_mma<1>, cudaFuncAttributeMaxDynamicSharedMemorySize, GSMEM);
    cudaFuncSetAttribute(gemm_mma<2>, cudaFuncAttributeMaxDynamicSharedMemorySize, GSMEM);
    cudaFuncSetAttribute(gemm_mma<3>, cudaFuncAttributeMaxDynamicSharedMemorySize, GSMEM);
    int attn_smem = (4 * 64 * ROWP + 3 * 64) * sizeof(float);
    cudaFuncSetAttribute(attn_k, cudaFuncAttributeMaxDynamicSharedMemorySize, attn_smem);

    // weight transposes (+ tf32 rounding)
    dim3 tb(32, 8);
    transpose_k<<<dim3(DM/32,  DM/32),  tb>>>(w_q, wqT, DM,  DM);
    transpose_k<<<dim3(DM/32,  DM/32),  tb>>>(w_k, wkT, DM,  DM);
    transpose_k<<<dim3(DM/32,  DM/32),  tb>>>(w_v, wvT, DM,  DM);
    transpose_k<<<dim3(DM/32,  DM/32),  tb>>>(w_o, woT, DM,  DM);
    transpose_k<<<dim3(DFF/32, DM/32),  tb>>>(w1,  w1T, DM,  DFF);
    transpose_k<<<dim3(DFF/32, DM/32),  tb>>>(w3,  w3T, DM,  DFF);
    transpose_k<<<dim3(DM/32,  DFF/32), tb>>>(w2,  w2T, DFF, DM);

    dim3 gD(DM / 128, MM / 128);                   // (8, 32)
    dim3 gF((DFF + 127) / 128, MM / 128);          // (22, 32)

    // 1. norm1
    rmsnorm_k<<<MM, 256>>>(x, g1, xn);
    // 2. q, k, v projections
    gemm_mma<0><<<gD, 256, GSMEM>>>(xn, wqT, nullptr, qp, MM, DM, DM);
    gemm_mma<0><<<gD, 256, GSMEM>>>(xn, wkT, nullptr, kp, MM, DM, DM);
    gemm_mma<0><<<gD, 256, GSMEM>>>(xn, wvT, nullptr, vp, MM, DM, DM);
    // 3. causal flash attention
    attn_k<<<dim3(SS / 64, NH, BB), 128, attn_smem>>>(qp, kp, vp, ap);
    // 4. h_res = x + attn @ w_o
    gemm_mma<1><<<gD, 256, GSMEM>>>(ap, woT, x, hres, MM, DM, DM);
    // 5. norm2
    rmsnorm_k<<<MM, 256>>>(hres, g2, hn);
    // 6. f1 = silu(hn @ w1)
    gemm_mma<2><<<gF, 256, GSMEM>>>(hn, w1T, nullptr, f1, MM, DFF, DM);
    // 7. f3 = f1 * (hn @ w3)
    gemm_mma<3><<<gF, 256, GSMEM>>>(hn, w3T, f1, f3, MM, DFF, DM);
    // 8. out = h_res + f3 @ w2
    gemm_mma<1><<<gD, 256, GSMEM>>>(f3, w2T, hres, out, MM, DM, DFF);
}

// round 4
// speedup vs baseline: 3.5032x; 1.5525x over previous
#include <cuda_runtime.h>
#include <cuda_bf16.h>
#include <math.h>
#include <stdint.h>

// Problem constants
#define BB 2
#define SS 2048
#define DM 1024
#define NH 16
#define DH 64
#define DFF 2752
#define MM (BB*SS)          // 4096 rows
#define EPSV 1e-5f
#define QKVS (3*DM)

// ---------------- scratch (static __device__, no allocation) ----------------
__device__ float g_xn  [MM*DM];
__device__ float g_qkv [MM*QKVS];
__device__ float g_attn[MM*DM];
__device__ float g_hres[MM*DM];
__device__ float g_hn  [MM*DM];
__device__ float g_f1  [MM*DFF];
__device__ float g_f3  [MM*DFF];
// transposed (tf32-rounded) weights, [N,K] row-major
__device__ float g_wqkvT[3*DM*DM];
__device__ float g_woT[DM*DM];
__device__ float g_w1T[DFF*DM];
__device__ float g_w3T[DFF*DM];
__device__ float g_w2T[DM*DFF];

// ---------------- helpers ----------------------------------------------------
__device__ __forceinline__ uint32_t s2u(const void* p) {
    uint32_t a;
    asm("{ .reg .u64 t; cvta.to.shared.u64 t, %1; cvt.u32.u64 %0, t; }"
        : "=r"(a) : "l"(p));
    return a;
}
__device__ __forceinline__ void cpa16(uint32_t dst, const void* src, uint32_t bytes) {
    asm volatile("cp.async.cg.shared.global [%0], [%1], 16, %2;"
                 :: "r"(dst), "l"(src), "r"(bytes) : "memory");
}
__device__ __forceinline__ void mma_tf32(float* c, const uint32_t* a, const uint32_t* b) {
    asm volatile("mma.sync.aligned.m16n8k8.row.col.f32.tf32.tf32.f32 "
        "{%0,%1,%2,%3}, {%4,%5,%6,%7}, {%8,%9}, {%0,%1,%2,%3};"
        : "+f"(c[0]), "+f"(c[1]), "+f"(c[2]), "+f"(c[3])
        : "r"(a[0]), "r"(a[1]), "r"(a[2]), "r"(a[3]), "r"(b[0]), "r"(b[1]));
}

// ---------------- RMSNorm ----------------------------------------------------
__global__ __launch_bounds__(256) void rmsnorm_k(const float* __restrict__ x,
                                                 const float* __restrict__ g,
                                                 float* __restrict__ out) {
    int row = blockIdx.x;
    const float* xr = x + (size_t)row * DM;
    float* orow = out + (size_t)row * DM;
    int t = threadIdx.x;
    float4 v = *(const float4*)&xr[t * 4];
    float ss = v.x*v.x + v.y*v.y + v.z*v.z + v.w*v.w;
    for (int o = 16; o > 0; o >>= 1) ss += __shfl_xor_sync(0xffffffffu, ss, o);
    __shared__ float wsum[8];
    if ((t & 31) == 0) wsum[t >> 5] = ss;
    __syncthreads();
    if (t < 8) {
        float s = wsum[t];
        for (int o = 4; o > 0; o >>= 1) s += __shfl_xor_sync(0xffu, s, o);
        if (t == 0) wsum[0] = s;
    }
    __syncthreads();
    float inv = rsqrtf(wsum[0] * (1.0f / DM) + EPSV);
    float4 gv = *(const float4*)&g[t * 4];
    float4 ov;
    ov.x = v.x * inv * gv.x; ov.y = v.y * inv * gv.y;
    ov.z = v.z * inv * gv.z; ov.w = v.w * inv * gv.w;
    *(float4*)&orow[t * 4] = ov;
}

// ---------------- Weight transpose (+ tf32 RN rounding) ---------------------
__global__ __launch_bounds__(256) void transpose_k(const float* __restrict__ in,
                                                   float* __restrict__ out,
                                                   int R, int C) {
    __shared__ float t[32][33];
    int bx = blockIdx.x * 32, by = blockIdx.y * 32;
    int tx = threadIdx.x, ty = threadIdx.y;
    #pragma unroll
    for (int i = 0; i < 32; i += 8) {
        float v = in[(size_t)(by + ty + i) * C + bx + tx];
        asm("cvt.rna.tf32.f32 %0, %0;" : "+f"(v));
        t[ty + i][tx] = v;
    }
    __syncthreads();
    #pragma unroll
    for (int i = 0; i < 32; i += 8)
        out[(size_t)(bx + ty + i) * R + by + tx] = t[tx][ty + i];
}

// ---------------- tf32 mma.sync GEMM -----------------------------------------
// C[M,N] = A[M,K] @ Wt[N,K]^T.   BM=BN=128, BK=32, 3-stage cp.async pipeline.
#define BKP 36
#define STG_F (128*BKP)
#define STG_B (STG_F*4)
#define STAGE_BYTES (2u*STG_B)
#define NSTAGE 3
#define GSMEM (NSTAGE*STAGE_BYTES)

template <int EPI>
__global__ __launch_bounds__(256) void gemm_mma(
    const float* __restrict__ A, const float* __restrict__ Bw,
    const float* __restrict__ extra, float* __restrict__ C,
    int M_, int N_, int K_)
{
    extern __shared__ float smf[];
    uint32_t smb = s2u(smf);
    int tid = threadIdx.x, lane = tid & 31, wid = tid >> 5;
    int wm = wid & 3, wn = wid >> 2;
    int g = lane >> 2, tg = lane & 3;
    int bm = blockIdx.y * 128, bn = blockIdx.x * 128;
    int nt = K_ >> 5;

    float acc[2][8][4];
    #pragma unroll
    for (int i = 0; i < 2; i++)
        #pragma unroll
        for (int j = 0; j < 8; j++)
            #pragma unroll
            for (int c = 0; c < 4; c++) acc[i][j][c] = 0.0f;

    auto load_stage = [&](int s, int t) {
        int k0 = t * 32;
        uint32_t sa = smb + s * STAGE_BYTES;
        uint32_t sbb = sa + STG_B;
        #pragma unroll
        for (int i = 0; i < 4; i++) {
            int e = tid + i * 256;
            int row = e >> 3, ch = e & 7;
            cpa16(sa + row * (BKP*4) + ch * 16,
                  A + (size_t)(bm + row) * K_ + k0 + ch * 4, 16u);
            int brow = bn + row;
            const float* bs = Bw + (size_t)(brow < N_ ? brow : 0) * K_ + k0 + ch * 4;
            cpa16(sbb + row * (BKP*4) + ch * 16, bs, brow < N_ ? 16u : 0u);
        }
    };

    load_stage(0, 0);
    asm volatile("cp.async.commit_group;");
    if (nt > 1) load_stage(1, 1);
    asm volatile("cp.async.commit_group;");

    for (int t = 0; t < nt; t++) {
        if (t + 2 < nt) load_stage((t + 2) % NSTAGE, t + 2);
        asm volatile("cp.async.commit_group;");
        asm volatile("cp.async.wait_group 2;");
        __syncthreads();

        const float* As = smf + (t % NSTAGE) * (STAGE_BYTES/4);
        const float* Bs = As + STG_F;
        #pragma unroll
        for (int ks = 0; ks < 4; ks++) {
            int kb = ks * 8;
            uint32_t af[2][4], bf[8][2];
            #pragma unroll
            for (int mt = 0; mt < 2; mt++) {
                int rb = wm * 32 + mt * 16;
                af[mt][0] = __float_as_uint(As[(rb + g    ) * BKP + kb + tg    ]);
                af[mt][1] = __float_as_uint(As[(rb + g + 8) * BKP + kb + tg    ]);
                af[mt][2] = __float_as_uint(As[(rb + g    ) * BKP + kb + tg + 4]);
                af[mt][3] = __float_as_uint(As[(rb + g + 8) * BKP + kb + tg + 4]);
            }
            #pragma unroll
            for (int ntile = 0; ntile < 8; ntile++) {
                int nb = wn * 64 + ntile * 8;
                bf[ntile][0] = __float_as_uint(Bs[(nb + g) * BKP + kb + tg    ]);
                bf[ntile][1] = __float_as_uint(Bs[(nb + g) * BKP + kb + tg + 4]);
            }
            #pragma unroll
            for (int mt = 0; mt < 2; mt++)
                #pragma unroll
                for (int ntile = 0; ntile < 8; ntile++)
                    mma_tf32(acc[mt][ntile], af[mt], bf[ntile]);
        }
        __syncthreads();
    }

    #pragma unroll
    for (int mt = 0; mt < 2; mt++) {
        int rr0 = bm + wm * 32 + mt * 16 + g;
        #pragma unroll
        for (int ntile = 0; ntile < 8; ntile++) {
            int cc = bn + wn * 64 + ntile * 8 + 2 * tg;
            if (cc >= N_) continue;
            #pragma unroll
            for (int half = 0; half < 2; half++) {
                int rr = rr0 + half * 8;
                float v0 = acc[mt][ntile][half * 2 + 0];
                float v1 = acc[mt][ntile][half * 2 + 1];
                size_t idx = (size_t)rr * N_ + cc;
                float2 o;
                if (EPI == 0) {
                    o = make_float2(v0, v1);
                } else if (EPI == 1) {
                    float2 e = *(const float2*)&extra[idx];
                    o = make_float2(e.x + v0, e.y + v1);
                } else if (EPI == 2) {
                    o.x = v0 / (1.0f + __expf(-v0));
                    o.y = v1 / (1.0f + __expf(-v1));
                } else {
                    float2 e = *(const float2*)&extra[idx];
                    o = make_float2(e.x * v0, e.y * v1);
                }
                *(float2*)&C[idx] = o;
            }
        }
    }
}

// ---------------- tf32 MMA flash attention (causal) -------------------------
// grid (S/64, NH, BB), 128 threads = 4 warps; warp w owns rows w*16..w*16+15.
#define ASTR 68
#define ASMEM (4*64*ASTR*4)
__global__ __launch_bounds__(128) void attn_mma(const float* __restrict__ qkv,
                                                float* __restrict__ o) {
    extern __shared__ float sm[];
    float* Qs = sm;                   // 64 x ASTR
    float* Ks = Qs + 64 * ASTR;
    float* Vt = Ks + 64 * ASTR;       // transposed: Vt[d][j]
    float* Ps = Vt + 64 * ASTR;

    int qt = blockIdx.x, h = blockIdx.y, b = blockIdx.z;
    int tid = threadIdx.x, lane = tid & 31, wid = tid >> 5;
    int g = lane >> 2, tg = lane & 3;
    const float scale = 0.125f;

    const float* qb = qkv + (size_t)b * SS * QKVS + h * DH;
    const float* kb = qb + DM;
    const float* vb = qb + 2 * DM;

    // load Q tile (64 x 64)
    #pragma unroll
    for (int i = 0; i < 8; i++) {
        int e4 = tid + i * 128;
        int r = e4 >> 4, c4 = (e4 & 15) * 4;
        float4 val = *(const float4*)&qb[(size_t)(qt * 64 + r) * QKVS + c4];
        *(float4*)&Qs[r * ASTR + c4] = val;
    }

    float oacc[8][4];
    #pragma unroll
    for (int i = 0; i < 8; i++)
        #pragma unroll
        for (int c = 0; c < 4; c++) oacc[i][c] = 0.0f;
    float mrow[2] = {-1e30f, -1e30f};
    float lrow[2] = {0.0f, 0.0f};

    int rb = wid * 16;

    for (int kt = 0; kt <= qt; kt++) {
        __syncthreads();
        #pragma unroll
        for (int i = 0; i < 8; i++) {
            int e4 = tid + i * 128;
            int r = e4 >> 4, c4 = (e4 & 15) * 4;
            size_t gidx = (size_t)(kt * 64 + r) * QKVS + c4;
            *(float4*)&Ks[r * ASTR + c4] = *(const float4*)&kb[gidx];
            float4 vv = *(const float4*)&vb[gidx];
            Vt[(c4+0) * ASTR + r] = vv.x;
            Vt[(c4+1) * ASTR + r] = vv.y;
            Vt[(c4+2) * ASTR + r] = vv.z;
            Vt[(c4+3) * ASTR + r] = vv.w;
        }
        __syncthreads();

        // S = Q K^T  (8 n-tiles x 8 k-steps)
        float sacc[8][4];
        #pragma unroll
        for (int i = 0; i < 8; i++)
            #pragma unroll
            for (int c = 0; c < 4; c++) sacc[i][c] = 0.0f;
        #pragma unroll
        for (int kk = 0; kk < 8; kk++) {
            int k8 = kk * 8;
            uint32_t af[4];
            af[0] = __float_as_uint(Qs[(rb + g    ) * ASTR + k8 + tg    ]);
            af[1] = __float_as_uint(Qs[(rb + g + 8) * ASTR + k8 + tg    ]);
            af[2] = __float_as_uint(Qs[(rb + g    ) * ASTR + k8 + tg + 4]);
            af[3] = __float_as_uint(Qs[(rb + g + 8) * ASTR + k8 + tg + 4]);
            #pragma unroll
            for (int nt = 0; nt < 8; nt++) {
                uint32_t bf[2];
                bf[0] = __float_as_uint(Ks[(nt * 8 + g) * ASTR + k8 + tg    ]);
                bf[1] = __float_as_uint(Ks[(nt * 8 + g) * ASTR + k8 + tg + 4]);
                mma_tf32(sacc[nt], af, bf);
            }
        }

        // scale + causal mask (only needed on diagonal tile)
        int row0 = qt * 64 + rb + g, row1 = row0 + 8;
        #pragma unroll
        for (int nt = 0; nt < 8; nt++) {
            int c0 = kt * 64 + nt * 8 + 2 * tg, c1 = c0 + 1;
            sacc[nt][0] *= scale; sacc[nt][1] *= scale;
            sacc[nt][2] *= scale; sacc[nt][3] *= scale;
            if (kt == qt) {
                if (c0 > row0) sacc[nt][0] = -1e30f;
                if (c1 > row0) sacc[nt][1] = -1e30f;
                if (c0 > row1) sacc[nt][2] = -1e30f;
                if (c1 > row1) sacc[nt][3] = -1e30f;
            }
        }

        // row max (within thread, then across quad tg via shfl)
        float rmax0 = -1e30f, rmax1 = -1e30f;
        #pragma unroll
        for (int nt = 0; nt < 8; nt++) {
            rmax0 = fmaxf(rmax0, fmaxf(sacc[nt][0], sacc[nt][1]));
            rmax1 = fmaxf(rmax1, fmaxf(sacc[nt][2], sacc[nt][3]));
        }
        rmax0 = fmaxf(rmax0, __shfl_xor_sync(0xffffffffu, rmax0, 1));
        rmax0 = fmaxf(rmax0, __shfl_xor_sync(0xffffffffu, rmax0, 2));
        rmax1 = fmaxf(rmax1, __shfl_xor_sync(0xffffffffu, rmax1, 1));
        rmax1 = fmaxf(rmax1, __shfl_xor_sync(0xffffffffu, rmax1, 2));

        float m0 = fmaxf(mrow[0], rmax0), m1 = fmaxf(mrow[1], rmax1);
        float r0 = __expf(mrow[0] - m0), r1 = __expf(mrow[1] - m1);
        mrow[0] = m0; mrow[1] = m1;

        float sum0 = 0.0f, sum1 = 0.0f;
        #pragma unroll
        for (int nt = 0; nt < 8; nt++) {
            float p0 = __expf(sacc[nt][0] - m0);
            float p1 = __expf(sacc[nt][1] - m0);
            float p2 = __expf(sacc[nt][2] - m1);
            float p3 = __expf(sacc[nt][3] - m1);
            sum0 += p0 + p1; sum1 += p2 + p3;
            int cl = nt * 8 + 2 * tg;
            *(float2*)&Ps[(rb + g    ) * ASTR + cl] = make_float2(p0, p1);
            *(float2*)&Ps[(rb + g + 8) * ASTR + cl] = make_float2(p2, p3);
        }
        sum0 += __shfl_xor_sync(0xffffffffu, sum0, 1);
        sum0 += __shfl_xor_sync(0xffffffffu, sum0, 2);
        sum1 += __shfl_xor_sync(0xffffffffu, sum1, 1);
        sum1 += __shfl_xor_sync(0xffffffffu, sum1, 2);
        lrow[0] = lrow[0] * r0 + sum0;
        lrow[1] = lrow[1] * r1 + sum1;

        #pragma unroll
        for (int dt = 0; dt < 8; dt++) {
            oacc[dt][0] *= r0; oacc[dt][1] *= r0;
            oacc[dt][2] *= r1; oacc[dt][3] *= r1;
        }
        __syncwarp();

        // O += P @ V   (A = Ps rows rb.., B = Vt[d][j])
        #pragma unroll
        for (int kk = 0; kk < 8; kk++) {
            int k8 = kk * 8;
            uint32_t af[4];
            af[0] = __float_as_uint(Ps[(rb + g    ) * ASTR + k8 + tg    ]);
            af[1] = __float_as_uint(Ps[(rb + g + 8) * ASTR + k8 + tg    ]);
            af[2] = __float_as_uint(Ps[(rb + g    ) * ASTR + k8 + tg + 4]);
            af[3] = __float_as_uint(Ps[(rb + g + 8) * ASTR + k8 + tg + 4]);
            #pragma unroll
            for (int dt = 0; dt < 8; dt++) {
                uint32_t bf[2];
                bf[0] = __float_as_uint(Vt[(dt * 8 + g) * ASTR + k8 + tg    ]);
                bf[1] = __float_as_uint(Vt[(dt * 8 + g) * ASTR + k8 + tg + 4]);
                mma_tf32(oacc[dt], af, bf);
            }
        }
    }

    float inv0 = 1.0f / lrow[0], inv1 = 1.0f / lrow[1];
    size_t orow0 = (size_t)b * SS + qt * 64 + rb + g;
    #pragma unroll
    for (int dt = 0; dt < 8; dt++) {
        int d = h * DH + dt * 8 + 2 * tg;
        *(float2*)&o[orow0 * DM + d] =
            make_float2(oacc[dt][0] * inv0, oacc[dt][1] * inv0);
        *(float2*)&o[(orow0 + 8) * DM + d] =
            make_float2(oacc[dt][2] * inv1, oacc[dt][3] * inv1);
    }
}

// ---------------- launch ------------------------------------------------------
extern "C" void kernel_launch(void* const* d_in, const int* in_sizes, int n_in,
                              void* d_out, int out_size) {
    const float* x   = (const float*)d_in[0];
    const float* g1  = (const float*)d_in[1];
    const float* g2  = (const float*)d_in[2];
    const float* w_q = (const float*)d_in[3];
    const float* w_k = (const float*)d_in[4];
    const float* w_v = (const float*)d_in[5];
    const float* w_o = (const float*)d_in[6];
    const float* w1  = (const float*)d_in[7];
    const float* w2  = (const float*)d_in[8];
    const float* w3  = (const float*)d_in[9];
    float* out = (float*)d_out;

    float *xn, *qkv, *ap, *hres, *hn, *f1, *f3;
    float *wqkvT, *woT, *w1T, *w3T, *w2T;
    cudaGetSymbolAddress((void**)&xn,    g_xn);
    cudaGetSymbolAddress((void**)&qkv,   g_qkv);
    cudaGetSymbolAddress((void**)&ap,    g_attn);
    cudaGetSymbolAddress((void**)&hres,  g_hres);
    cudaGetSymbolAddress((void**)&hn,    g_hn);
    cudaGetSymbolAddress((void**)&f1,    g_f1);
    cudaGetSymbolAddress((void**)&f3,    g_f3);
    cudaGetSymbolAddress((void**)&wqkvT, g_wqkvT);
    cudaGetSymbolAddress((void**)&woT,   g_woT);
    cudaGetSymbolAddress((void**)&w1T,   g_w1T);
    cudaGetSymbolAddress((void**)&w3T,   g_w3T);
    cudaGetSymbolAddress((void**)&w2T,   g_w2T);

    cudaFuncSetAttribute(gemm_mma<0>, cudaFuncAttributeMaxDynamicSharedMemorySize, GSMEM);
    cudaFuncSetAttribute(gemm_mma<1>, cudaFuncAttributeMaxDynamicSharedMemorySize, GSMEM);
    cudaFuncSetAttribute(gemm_mma<2>, cudaFuncAttributeMaxDynamicSharedMemorySize, GSMEM);
    cudaFuncSetAttribute(gemm_mma<3>, cudaFuncAttributeMaxDynamicSharedMemorySize, GSMEM);
    cudaFuncSetAttribute(attn_mma, cudaFuncAttributeMaxDynamicSharedMemorySize, ASMEM);

    // weight transposes (+ tf32 rounding); q/k/v stacked into one [3*DM, DM]
    dim3 tb(32, 8);
    transpose_k<<<dim3(DM/32,  DM/32),  tb>>>(w_q, wqkvT,            DM,  DM);
    transpose_k<<<dim3(DM/32,  DM/32),  tb>>>(w_k, wqkvT + DM*DM,    DM,  DM);
    transpose_k<<<dim3(DM/32,  DM/32),  tb>>>(w_v, wqkvT + 2*DM*DM,  DM,  DM);
    transpose_k<<<dim3(DM/32,  DM/32),  tb>>>(w_o, woT, DM,  DM);
    transpose_k<<<dim3(DFF/32, DM/32),  tb>>>(w1,  w1T, DM,  DFF);
    transpose_k<<<dim3(DFF/32, DM/32),  tb>>>(w3,  w3T, DM,  DFF);
    transpose_k<<<dim3(DM/32,  DFF/32), tb>>>(w2,  w2T, DFF, DM);

    dim3 gQKV(QKVS / 128, MM / 128);               // (24, 32)
    dim3 gD(DM / 128, MM / 128);                   // (8, 32)
    dim3 gF((DFF + 127) / 128, MM / 128);          // (22, 32)

    // 1. norm1
    rmsnorm_k<<<MM, 256>>>(x, g1, xn);
    // 2. fused qkv projection
    gemm_mma<0><<<gQKV, 256, GSMEM>>>(xn, wqkvT, nullptr, qkv, MM, QKVS, DM);
    // 3. causal flash attention (tensor cores)
    attn_mma<<<dim3(SS / 64, NH, BB), 128, ASMEM>>>(qkv, ap);
    // 4. h_res = x + attn @ w_o
    gemm_mma<1><<<gD, 256, GSMEM>>>(ap, woT, x, hres, MM, DM, DM);
    // 5. norm2
    rmsnorm_k<<<MM, 256>>>(hres, g2, hn);
    // 6. f1 = silu(hn @ w1)
    gemm_mma<2><<<gF, 256, GSMEM>>>(hn, w1T, nullptr, f1, MM, DFF, DM);
    // 7. f3 = f1 * (hn @ w3)
    gemm_mma<3><<<gF, 256, GSMEM>>>(hn, w3T, f1, f3, MM, DFF, DM);
    // 8. out = h_res + f3 @ w2
    gemm_mma<1><<<gD, 256, GSMEM>>>(f3, w2T, hres, out, MM, DM, DFF);
}

// round 6
// speedup vs baseline: 5.3777x; 1.5351x over previous
#include <cuda_runtime.h>
#include <cuda_fp16.h>
#include <math.h>
#include <stdint.h>

// Problem constants
#define BB 2
#define SS 2048
#define DM 1024
#define NH 16
#define DH 64
#define DFF 2752
#define MM (BB*SS)          // 4096 rows
#define EPSV 1e-5f
#define QKVS (3*DM)

// ---------------- scratch (static __device__, no allocation) ----------------
__device__ __align__(16) __half g_xn  [MM*DM];
__device__ __align__(16) __half g_qkv [MM*QKVS];
__device__ __align__(16) __half g_attn[MM*DM];
__device__ float  g_hres[MM*DM];
__device__ __align__(16) __half g_hn  [MM*DM];
__device__ float  g_f1  [MM*DFF];
__device__ __align__(16) __half g_f3  [MM*DFF];
// transposed fp16 weights, [N,K] row-major
__device__ __align__(16) __half g_wqkvT[3*DM*DM];
__device__ __align__(16) __half g_woT[DM*DM];
__device__ __align__(16) __half g_w1T[DFF*DM];
__device__ __align__(16) __half g_w3T[DFF*DM];
__device__ __align__(16) __half g_w2T[DM*DFF];

// ---------------- helpers ----------------------------------------------------
__device__ __forceinline__ uint32_t s2u(const void* p) {
    uint32_t a;
    asm("{ .reg .u64 t; cvta.to.shared.u64 t, %1; cvt.u32.u64 %0, t; }"
        : "=r"(a) : "l"(p));
    return a;
}
__device__ __forceinline__ void cpa16(uint32_t dst, const void* src, uint32_t bytes) {
    asm volatile("cp.async.cg.shared.global [%0], [%1], 16, %2;"
                 :: "r"(dst), "l"(src), "r"(bytes) : "memory");
}
__device__ __forceinline__ void mma_f16(float* c, const uint32_t* a, const uint32_t* b) {
    asm volatile("mma.sync.aligned.m16n8k16.row.col.f32.f16.f16.f32 "
        "{%0,%1,%2,%3}, {%4,%5,%6,%7}, {%8,%9}, {%0,%1,%2,%3};"
        : "+f"(c[0]), "+f"(c[1]), "+f"(c[2]), "+f"(c[3])
        : "r"(a[0]), "r"(a[1]), "r"(a[2]), "r"(a[3]), "r"(b[0]), "r"(b[1]));
}

// ---------------- RMSNorm (fp32 in -> fp16 out) ------------------------------
__global__ __launch_bounds__(256) void rmsnorm_h(const float* __restrict__ x,
                                                 const float* __restrict__ g,
                                                 __half* __restrict__ out) {
    int row = blockIdx.x;
    const float* xr = x + (size_t)row * DM;
    __half* orow = out + (size_t)row * DM;
    int t = threadIdx.x;
    float4 v = *(const float4*)&xr[t * 4];
    float ss = v.x*v.x + v.y*v.y + v.z*v.z + v.w*v.w;
    for (int o = 16; o > 0; o >>= 1) ss += __shfl_xor_sync(0xffffffffu, ss, o);
    __shared__ float wsum[8];
    if ((t & 31) == 0) wsum[t >> 5] = ss;
    __syncthreads();
    if (t < 8) {
        float s = wsum[t];
        for (int o = 4; o > 0; o >>= 1) s += __shfl_xor_sync(0xffu, s, o);
        if (t == 0) wsum[0] = s;
    }
    __syncthreads();
    float inv = rsqrtf(wsum[0] * (1.0f / DM) + EPSV);
    float4 gv = *(const float4*)&g[t * 4];
    ((__half2*)orow)[t*2  ] = __floats2half2_rn(v.x*inv*gv.x, v.y*inv*gv.y);
    ((__half2*)orow)[t*2+1] = __floats2half2_rn(v.z*inv*gv.z, v.w*inv*gv.w);
}

// ---------------- Weight transpose fp32 -> fp16 [N,K] ------------------------
__global__ __launch_bounds__(256) void transpose_k(const float* __restrict__ in,
                                                   __half* __restrict__ out,
                                                   int R, int C) {
    __shared__ float t[32][33];
    int bx = blockIdx.x * 32, by = blockIdx.y * 32;
    int tx = threadIdx.x, ty = threadIdx.y;
    #pragma unroll
    for (int i = 0; i < 32; i += 8)
        t[ty + i][tx] = in[(size_t)(by + ty + i) * C + bx + tx];
    __syncthreads();
    #pragma unroll
    for (int i = 0; i < 32; i += 8)
        out[(size_t)(bx + ty + i) * R + by + tx] = __float2half(t[tx][ty + i]);
}

// ---------------- fp16 mma.sync GEMM -----------------------------------------
// C[M,N] = A[M,K] @ Wt[N,K]^T.   BM=BN=128, BK=32, 4-stage cp.async.
// EPI: 0 plain->half, 1 residual(+extra)->float, 2 silu->float, 3 gate(*extra)->half
#define BKH 40                       // padded K stride (halves); 20 words
#define OPB (128*BKH*2)              // bytes per operand per stage (10240)
#define STAGE_BYTES (2u*OPB)
#define NSTAGE 4
#define GSMEM (NSTAGE*STAGE_BYTES)   // 81920

template <int EPI>
__global__ __launch_bounds__(256) void gemm_mma(
    const __half* __restrict__ A, const __half* __restrict__ Bw,
    const float* __restrict__ extra, void* __restrict__ Cv,
    int M_, int N_, int K_)
{
    extern __shared__ char smc[];
    uint32_t smb = s2u(smc);
    int tid = threadIdx.x, lane = tid & 31, wid = tid >> 5;
    int wm = wid & 3, wn = wid >> 2;
    int g = lane >> 2, tg = lane & 3;
    int bm = blockIdx.y * 128, bn = blockIdx.x * 128;
    int nt = K_ >> 5;

    float acc[2][8][4];
    #pragma unroll
    for (int i = 0; i < 2; i++)
        #pragma unroll
        for (int j = 0; j < 8; j++)
            #pragma unroll
            for (int c = 0; c < 4; c++) acc[i][j][c] = 0.0f;

    auto load_stage = [&](int s, int t) {
        int k0 = t * 32;
        uint32_t sa = smb + s * STAGE_BYTES;
        uint32_t sbb = sa + OPB;
        #pragma unroll
        for (int i = 0; i < 2; i++) {
            int e = tid + i * 256;            // 512 chunks per operand
            int row = e >> 2, ch = e & 3;
            cpa16(sa + row * (BKH*2) + ch * 16,
                  A + (size_t)(bm + row) * K_ + k0 + ch * 8, 16u);
            int brow = bn + row;
            const __half* bs = Bw + (size_t)(brow < N_ ? brow : 0) * K_ + k0 + ch * 8;
            cpa16(sbb + row * (BKH*2) + ch * 16, bs, brow < N_ ? 16u : 0u);
        }
    };

    load_stage(0, 0); asm volatile("cp.async.commit_group;");
    if (nt > 1) load_stage(1, 1); asm volatile("cp.async.commit_group;");
    if (nt > 2) load_stage(2, 2); asm volatile("cp.async.commit_group;");

    for (int t = 0; t < nt; t++) {
        if (t + 3 < nt) load_stage((t + 3) & 3, t + 3);
        asm volatile("cp.async.commit_group;");
        asm volatile("cp.async.wait_group 3;");
        __syncthreads();

        const uint32_t* As = (const uint32_t*)(smc + (t & 3) * STAGE_BYTES);
        const uint32_t* Bs = As + OPB/4;
        #pragma unroll
        for (int ks = 0; ks < 2; ks++) {
            int kb = ks * 8;                   // word offset
            uint32_t af[2][4], bf[8][2];
            #pragma unroll
            for (int mt = 0; mt < 2; mt++) {
                int rb = wm * 32 + mt * 16;
                af[mt][0] = As[(rb + g    ) * 20 + kb + tg    ];
                af[mt][1] = As[(rb + g + 8) * 20 + kb + tg    ];
                af[mt][2] = As[(rb + g    ) * 20 + kb + tg + 4];
                af[mt][3] = As[(rb + g + 8) * 20 + kb + tg + 4];
            }
            #pragma unroll
            for (int ntile = 0; ntile < 8; ntile++) {
                int nb = wn * 64 + ntile * 8;
                bf[ntile][0] = Bs[(nb + g) * 20 + kb + tg    ];
                bf[ntile][1] = Bs[(nb + g) * 20 + kb + tg + 4];
            }
            #pragma unroll
            for (int mt = 0; mt < 2; mt++)
                #pragma unroll
                for (int ntile = 0; ntile < 8; ntile++)
                    mma_f16(acc[mt][ntile], af[mt], bf[ntile]);
        }
        __syncthreads();
    }

    #pragma unroll
    for (int mt = 0; mt < 2; mt++) {
        int rr0 = bm + wm * 32 + mt * 16 + g;
        #pragma unroll
        for (int ntile = 0; ntile < 8; ntile++) {
            int cc = bn + wn * 64 + ntile * 8 + 2 * tg;
            if (cc >= N_) continue;
            #pragma unroll
            for (int half_ = 0; half_ < 2; half_++) {
                int rr = rr0 + half_ * 8;
                float v0 = acc[mt][ntile][half_ * 2 + 0];
                float v1 = acc[mt][ntile][half_ * 2 + 1];
                size_t idx = (size_t)rr * N_ + cc;
                if (EPI == 0) {
                    *(__half2*)((__half*)Cv + idx) = __floats2half2_rn(v0, v1);
                } else if (EPI == 1) {
                    float2 e = *(const float2*)&extra[idx];
                    *(float2*)((float*)Cv + idx) = make_float2(e.x + v0, e.y + v1);
                } else if (EPI == 2) {
                    *(float2*)((float*)Cv + idx) = make_float2(
                        v0 / (1.0f + __expf(-v0)), v1 / (1.0f + __expf(-v1)));
                } else {
                    float2 e = *(const float2*)&extra[idx];
                    *(__half2*)((__half*)Cv + idx) = __floats2half2_rn(e.x * v0, e.y * v1);
                }
            }
        }
    }
}

// ---------------- fp16 MMA flash attention (causal) -------------------------
// grid (S/64, NH, BB), 128 threads = 4 warps; warp w owns rows w*16..w*16+15.
#define ASTR 72                      // halves; 36 words
#define ATILE (64*ASTR)              // halves per tile
#define ASMEM (4*ATILE*2)            // bytes (Qs,Ks,Vt,Ps)
__global__ __launch_bounds__(128) void attn_mma(const __half* __restrict__ qkv,
                                                __half* __restrict__ o) {
    extern __shared__ __half sma[];
    __half* Qs = sma;
    __half* Ks = Qs + ATILE;
    __half* Vt = Ks + ATILE;         // transposed: Vt[d][j]
    __half* Ps = Vt + ATILE;

    int qt = blockIdx.x, h = blockIdx.y, b = blockIdx.z;
    int tid = threadIdx.x, lane = tid & 31, wid = tid >> 5;
    int g = lane >> 2, tg = lane & 3;
    const float scale = 0.125f;

    const __half* qb = qkv + (size_t)b * SS * QKVS + h * DH;
    const __half* kb = qb + DM;
    const __half* vb = qb + 2 * DM;

    // load Q tile (64 x 64 halves): 512 8-half chunks / 128 threads
    #pragma unroll
    for (int i = 0; i < 4; i++) {
        int e = tid + i * 128;
        int r = e >> 3, c8 = (e & 7) * 8;
        *(uint4*)&Qs[r * ASTR + c8] =
            *(const uint4*)&qb[(size_t)(qt * 64 + r) * QKVS + c8];
    }

    float oacc[8][4];
    #pragma unroll
    for (int i = 0; i < 8; i++)
        #pragma unroll
        for (int c = 0; c < 4; c++) oacc[i][c] = 0.0f;
    float mrow[2] = {-1e30f, -1e30f};
    float lrow[2] = {0.0f, 0.0f};

    int rb = wid * 16;
    const uint32_t* Qw = (const uint32_t*)Qs;
    const uint32_t* Kw = (const uint32_t*)Ks;
    const uint32_t* Vw = (const uint32_t*)Vt;
    const uint32_t* Pw = (const uint32_t*)Ps;

    for (int kt = 0; kt <= qt; kt++) {
        __syncthreads();
        #pragma unroll
        for (int i = 0; i < 4; i++) {
            int e = tid + i * 128;
            int r = e >> 3, c8 = (e & 7) * 8;
            size_t gidx = (size_t)(kt * 64 + r) * QKVS + c8;
            *(uint4*)&Ks[r * ASTR + c8] = *(const uint4*)&kb[gidx];
            union { uint4 u; __half hh[8]; } vv;
            vv.u = *(const uint4*)&vb[gidx];
            #pragma unroll
            for (int j = 0; j < 8; j++) Vt[(c8 + j) * ASTR + r] = vv.hh[j];
        }
        __syncthreads();

        // S = Q K^T  (8 n-tiles x 4 k16-steps)
        float sacc[8][4];
        #pragma unroll
        for (int i = 0; i < 8; i++)
            #pragma unroll
            for (int c = 0; c < 4; c++) sacc[i][c] = 0.0f;
        #pragma unroll
        for (int kk = 0; kk < 4; kk++) {
            int kb8 = kk * 8;                  // word offset
            uint32_t af[4];
            af[0] = Qw[(rb + g    ) * 36 + kb8 + tg    ];
            af[1] = Qw[(rb + g + 8) * 36 + kb8 + tg    ];
            af[2] = Qw[(rb + g    ) * 36 + kb8 + tg + 4];
            af[3] = Qw[(rb + g + 8) * 36 + kb8 + tg + 4];
            #pragma unroll
            for (int nt = 0; nt < 8; nt++) {
                uint32_t bf[2];
                bf[0] = Kw[(nt * 8 + g) * 36 + kb8 + tg    ];
                bf[1] = Kw[(nt * 8 + g) * 36 + kb8 + tg + 4];
                mma_f16(sacc[nt], af, bf);
            }
        }

        // scale + causal mask
        int row0 = qt * 64 + rb + g, row1 = row0 + 8;
        #pragma unroll
        for (int nt = 0; nt < 8; nt++) {
            int c0 = kt * 64 + nt * 8 + 2 * tg, c1 = c0 + 1;
            sacc[nt][0] *= scale; sacc[nt][1] *= scale;
            sacc[nt][2] *= scale; sacc[nt][3] *= scale;
            if (kt == qt) {
                if (c0 > row0) sacc[nt][0] = -1e30f;
                if (c1 > row0) sacc[nt][1] = -1e30f;
                if (c0 > row1) sacc[nt][2] = -1e30f;
                if (c1 > row1) sacc[nt][3] = -1e30f;
            }
        }

        float rmax0 = -1e30f, rmax1 = -1e30f;
        #pragma unroll
        for (int nt = 0; nt < 8; nt++) {
            rmax0 = fmaxf(rmax0, fmaxf(sacc[nt][0], sacc[nt][1]));
            rmax1 = fmaxf(rmax1, fmaxf(sacc[nt][2], sacc[nt][3]));
        }
        rmax0 = fmaxf(rmax0, __shfl_xor_sync(0xffffffffu, rmax0, 1));
        rmax0 = fmaxf(rmax0, __shfl_xor_sync(0xffffffffu, rmax0, 2));
        rmax1 = fmaxf(rmax1, __shfl_xor_sync(0xffffffffu, rmax1, 1));
        rmax1 = fmaxf(rmax1, __shfl_xor_sync(0xffffffffu, rmax1, 2));

        float m0 = fmaxf(mrow[0], rmax0), m1 = fmaxf(mrow[1], rmax1);
        float r0 = __expf(mrow[0] - m0), r1 = __expf(mrow[1] - m1);
        mrow[0] = m0; mrow[1] = m1;

        float sum0 = 0.0f, sum1 = 0.0f;
        #pragma unroll
        for (int nt = 0; nt < 8; nt++) {
            float p0 = __expf(sacc[nt][0] - m0);
            float p1 = __expf(sacc[nt][1] - m0);
            float p2 = __expf(sacc[nt][2] - m1);
            float p3 = __expf(sacc[nt][3] - m1);
            sum0 += p0 + p1; sum1 += p2 + p3;
            int cl = nt * 8 + 2 * tg;
            *(__half2*)&Ps[(rb + g    ) * ASTR + cl] = __floats2half2_rn(p0, p1);
            *(__half2*)&Ps[(rb + g + 8) * ASTR + cl] = __floats2half2_rn(p2, p3);
        }
        sum0 += __shfl_xor_sync(0xffffffffu, sum0, 1);
        sum0 += __shfl_xor_sync(0xffffffffu, sum0, 2);
        sum1 += __shfl_xor_sync(0xffffffffu, sum1, 1);
        sum1 += __shfl_xor_sync(0xffffffffu, sum1, 2);
        lrow[0] = lrow[0] * r0 + sum0;
        lrow[1] = lrow[1] * r1 + sum1;

        #pragma unroll
        for (int dt = 0; dt < 8; dt++) {
            oacc[dt][0] *= r0; oacc[dt][1] *= r0;
            oacc[dt][2] *= r1; oacc[dt][3] *= r1;
        }
        __syncwarp();

        // O += P @ V
        #pragma unroll
        for (int kk = 0; kk < 4; kk++) {
            int kb8 = kk * 8;
            uint32_t af[4];
            af[0] = Pw[(rb + g    ) * 36 + kb8 + tg    ];
            af[1] = Pw[(rb + g + 8) * 36 + kb8 + tg    ];
            af[2] = Pw[(rb + g    ) * 36 + kb8 + tg + 4];
            af[3] = Pw[(rb + g + 8) * 36 + kb8 + tg + 4];
            #pragma unroll
            for (int dt = 0; dt < 8; dt++) {
                uint32_t bf[2];
                bf[0] = Vw[(dt * 8 + g) * 36 + kb8 + tg    ];
                bf[1] = Vw[(dt * 8 + g) * 36 + kb8 + tg + 4];
                mma_f16(oacc[dt], af, bf);
            }
        }
    }

    float inv0 = 1.0f / lrow[0], inv1 = 1.0f / lrow[1];
    size_t orow0 = (size_t)b * SS + qt * 64 + rb + g;
    #pragma unroll
    for (int dt = 0; dt < 8; dt++) {
        int d = h * DH + dt * 8 + 2 * tg;
        *(__half2*)&o[orow0 * DM + d] =
            __floats2half2_rn(oacc[dt][0] * inv0, oacc[dt][1] * inv0);
        *(__half2*)&o[(orow0 + 8) * DM + d] =
            __floats2half2_rn(oacc[dt][2] * inv1, oacc[dt][3] * inv1);
    }
}

// ---------------- launch ------------------------------------------------------
extern "C" void kernel_launch(void* const* d_in, const int* in_sizes, int n_in,
                              void* d_out, int out_size) {
    const float* x   = (const float*)d_in[0];
    const float* g1  = (const float*)d_in[1];
    const float* g2  = (const float*)d_in[2];
    const float* w_q = (const float*)d_in[3];
    const float* w_k = (const float*)d_in[4];
    const float* w_v = (const float*)d_in[5];
    const float* w_o = (const float*)d_in[6];
    const float* w1  = (const float*)d_in[7];
    const float* w2  = (const float*)d_in[8];
    const float* w3  = (const float*)d_in[9];
    float* out = (float*)d_out;

    __half *xn, *qkv, *ap, *hn, *f3, *wqkvT, *woT, *w1T, *w3T, *w2T;
    float *hres, *f1;
    cudaGetSymbolAddress((void**)&xn,    g_xn);
    cudaGetSymbolAddress((void**)&qkv,   g_qkv);
    cudaGetSymbolAddress((void**)&ap,    g_attn);
    cudaGetSymbolAddress((void**)&hres,  g_hres);
    cudaGetSymbolAddress((void**)&hn,    g_hn);
    cudaGetSymbolAddress((void**)&f1,    g_f1);
    cudaGetSymbolAddress((void**)&f3,    g_f3);
    cudaGetSymbolAddress((void**)&wqkvT, g_wqkvT);
    cudaGetSymbolAddress((void**)&woT,   g_woT);
    cudaGetSymbolAddress((void**)&w1T,   g_w1T);
    cudaGetSymbolAddress((void**)&w3T,   g_w3T);
    cudaGetSymbolAddress((void**)&w2T,   g_w2T);

    cudaFuncSetAttribute(gemm_mma<0>, cudaFuncAttributeMaxDynamicSharedMemorySize, GSMEM);
    cudaFuncSetAttribute(gemm_mma<1>, cudaFuncAttributeMaxDynamicSharedMemorySize, GSMEM);
    cudaFuncSetAttribute(gemm_mma<2>, cudaFuncAttributeMaxDynamicSharedMemorySize, GSMEM);
    cudaFuncSetAttribute(gemm_mma<3>, cudaFuncAttributeMaxDynamicSharedMemorySize, GSMEM);
    cudaFuncSetAttribute(attn_mma, cudaFuncAttributeMaxDynamicSharedMemorySize, ASMEM);

    // weight transposes to fp16 [N,K]; q/k/v stacked into one [3*DM, DM]
    dim3 tb(32, 8);
    transpose_k<<<dim3(DM/32,  DM/32),  tb>>>(w_q, wqkvT,           DM,  DM);
    transpose_k<<<dim3(DM/32,  DM/32),  tb>>>(w_k, wqkvT + DM*DM,   DM,  DM);
    transpose_k<<<dim3(DM/32,  DM/32),  tb>>>(w_v, wqkvT + 2*DM*DM, DM,  DM);
    transpose_k<<<dim3(DM/32,  DM/32),  tb>>>(w_o, woT, DM,  DM);
    transpose_k<<<dim3(DFF/32, DM/32),  tb>>>(w1,  w1T, DM,  DFF);
    transpose_k<<<dim3(DFF/32, DM/32),  tb>>>(w3,  w3T, DM,  DFF);
    transpose_k<<<dim3(DM/32,  DFF/32), tb>>>(w2,  w2T, DFF, DM);

    dim3 gQKV(QKVS / 128, MM / 128);               // (24, 32)
    dim3 gD(DM / 128, MM / 128);                   // (8, 32)
    dim3 gF((DFF + 127) / 128, MM / 128);          // (22, 32)

    // 1. norm1 -> fp16
    rmsnorm_h<<<MM, 256>>>(x, g1, xn);
    // 2. fused qkv projection -> fp16
    gemm_mma<0><<<gQKV, 256, GSMEM>>>(xn, wqkvT, nullptr, qkv, MM, QKVS, DM);
    // 3. causal flash attention -> fp16
    attn_mma<<<dim3(SS / 64, NH, BB), 128, ASMEM>>>(qkv, ap);
    // 4. h_res = x + attn @ w_o  (fp32)
    gemm_mma<1><<<gD, 256, GSMEM>>>(ap, woT, x, hres, MM, DM, DM);
    // 5. norm2 -> fp16
    rmsnorm_h<<<MM, 256>>>(hres, g2, hn);
    // 6. f1 = silu(hn @ w1)  (fp32)
    gemm_mma<2><<<gF, 256, GSMEM>>>(hn, w1T, nullptr, f1, MM, DFF, DM);
    // 7. f3 = f1 * (hn @ w3) -> fp16
    gemm_mma<3><<<gF, 256, GSMEM>>>(hn, w3T, f1, f3, MM, DFF, DM);
    // 8. out = h_res + f3 @ w2  (fp32)
    gemm_mma<1><<<gD, 256, GSMEM>>>(f3, w2T, hres, out, MM, DM, DFF);
}

// round 9
// speedup vs baseline: 7.1556x; 1.3306x over previous
#include <cuda_runtime.h>
#include <cuda_fp16.h>
#include <math.h>
#include <stdint.h>
#include <string.h>

// Problem constants
#define BB 2
#define SS 2048
#define DM 1024
#define NH 16
#define DH 64
#define DFF 2752
#define MM (BB*SS)          // 4096 rows
#define EPSV 1e-5f
#define QKVS (3*DM)

// ---------------- scratch (static __device__, no allocation) ----------------
__device__ __align__(16) __half g_xn  [MM*DM];
__device__ __align__(16) __half g_qkv [MM*QKVS];
__device__ __align__(16) __half g_attn[MM*DM];
__device__ float  g_hres[MM*DM];
__device__ __align__(16) __half g_hn  [MM*DM];
__device__ __align__(16) __half g_f3  [MM*DFF];
// transposed fp16 weights, [N,K] row-major
__device__ __align__(16) __half g_wqkvT[3*DM*DM];
__device__ __align__(16) __half g_woT[DM*DM];
__device__ __align__(16) __half g_w1T[DFF*DM];
__device__ __align__(16) __half g_w3T[DFF*DM];
__device__ __align__(16) __half g_w2T[DM*DFF];

// ---------------- helpers ----------------------------------------------------
__device__ __forceinline__ uint32_t s2u(const void* p) {
    uint32_t a;
    asm("{ .reg .u64 t; cvta.to.shared.u64 t, %1; cvt.u32.u64 %0, t; }"
        : "=r"(a) : "l"(p));
    return a;
}
__device__ __forceinline__ void cpa16(uint32_t dst, const void* src) {
    asm volatile("cp.async.cg.shared.global [%0], [%1], 16;"
                 :: "r"(dst), "l"(src) : "memory");
}
__device__ __forceinline__ void mma_f16(float* c, const uint32_t* a, const uint32_t* b) {
    asm volatile("mma.sync.aligned.m16n8k16.row.col.f32.f16.f16.f32 "
        "{%0,%1,%2,%3}, {%4,%5,%6,%7}, {%8,%9}, {%0,%1,%2,%3};"
        : "+f"(c[0]), "+f"(c[1]), "+f"(c[2]), "+f"(c[3])
        : "r"(a[0]), "r"(a[1]), "r"(a[2]), "r"(a[3]), "r"(b[0]), "r"(b[1]));
}
__device__ __forceinline__ void ldm4(uint32_t* d, uint32_t addr) {
    asm volatile("ldmatrix.sync.aligned.m8n8.x4.shared.b16 {%0,%1,%2,%3}, [%4];"
        : "=r"(d[0]), "=r"(d[1]), "=r"(d[2]), "=r"(d[3]) : "r"(addr));
}
__device__ __forceinline__ void ldm4t(uint32_t* d, uint32_t addr) {
    asm volatile("ldmatrix.sync.aligned.m8n8.x4.trans.shared.b16 {%0,%1,%2,%3}, [%4];"
        : "=r"(d[0]), "=r"(d[1]), "=r"(d[2]), "=r"(d[3]) : "r"(addr));
}
// pack two floats -> fp16x2 bit pattern in a uint32
__device__ __forceinline__ uint32_t h2u(float lo, float hi) {
    uint32_t r;
    asm("cvt.rn.f16x2.f32 %0, %1, %2;" : "=r"(r) : "f"(hi), "f"(lo));
    return r;
}

// ---------------- RMSNorm (fp32 in -> fp16 out) ------------------------------
__global__ __launch_bounds__(256) void rmsnorm_h(const float* __restrict__ x,
                                                 const float* __restrict__ g,
                                                 __half* __restrict__ out) {
    int row = blockIdx.x;
    const float* xr = x + (size_t)row * DM;
    __half* orow = out + (size_t)row * DM;
    int t = threadIdx.x;
    float4 v = *(const float4*)&xr[t * 4];
    float ss = v.x*v.x + v.y*v.y + v.z*v.z + v.w*v.w;
    for (int o = 16; o > 0; o >>= 1) ss += __shfl_xor_sync(0xffffffffu, ss, o);
    __shared__ float wsum[8];
    if ((t & 31) == 0) wsum[t >> 5] = ss;
    __syncthreads();
    if (t < 8) {
        float s = wsum[t];
        for (int o = 4; o > 0; o >>= 1) s += __shfl_xor_sync(0xffu, s, o);
        if (t == 0) wsum[0] = s;
    }
    __syncthreads();
    float inv = rsqrtf(wsum[0] * (1.0f / DM) + EPSV);
    float4 gv = *(const float4*)&g[t * 4];
    ((__half2*)orow)[t*2  ] = __floats2half2_rn(v.x*inv*gv.x, v.y*inv*gv.y);
    ((__half2*)orow)[t*2+1] = __floats2half2_rn(v.z*inv*gv.z, v.w*inv*gv.w);
}

// ---------------- Weight transpose fp32 -> fp16 [N,K] ------------------------
__global__ __launch_bounds__(256) void transpose_k(const float* __restrict__ in,
                                                   __half* __restrict__ out,
                                                   int R, int C) {
    __shared__ float t[32][33];
    int bx = blockIdx.x * 32, by = blockIdx.y * 32;
    int tx = threadIdx.x, ty = threadIdx.y;
    #pragma unroll
    for (int i = 0; i < 32; i += 8)
        t[ty + i][tx] = in[(size_t)(by + ty + i) * C + bx + tx];
    __syncthreads();
    #pragma unroll
    for (int i = 0; i < 32; i += 8)
        out[(size_t)(bx + ty + i) * R + by + tx] = __float2half(t[tx][ty + i]);
}

// ---------------- fp16 mma.sync GEMM (ldmatrix) ------------------------------
// C[M,N] = A[M,K] @ Wt[N,K]^T.  BM=BN=128, BK=32, 4-stage cp.async.
// All shapes: M%128==0, N%128==0, K%32==0.
// EPI: 0 plain->half, 1 residual(+extra)->float
#define BKH 40                       // padded K stride (halves) = 80 bytes
#define OPB (128*BKH*2)              // bytes per operand per stage (10240)
#define STAGE_BYTES (2u*OPB)
#define GSMEM (4u*STAGE_BYTES)       // 81920

template <int EPI>
__global__ __launch_bounds__(256) void gemm_mma(
    const __half* __restrict__ A, const __half* __restrict__ Bw,
    const float* __restrict__ extra, void* __restrict__ Cv,
    int M_, int N_, int K_)
{
    extern __shared__ char smc[];
    uint32_t smb = s2u(smc);
    int tid = threadIdx.x, lane = tid & 31, wid = tid >> 5;
    int wm = wid & 3, wn = wid >> 2;
    int g = lane >> 2, tg = lane & 3;
    int bm = blockIdx.y * 128, bn = blockIdx.x * 128;
    int nt = K_ >> 5;

    // ldmatrix per-lane offsets
    int l15 = lane & 15, lk16 = (lane >> 4) * 16;          // A
    int browoff = ((lane >> 4) & 1) * 8 + (lane & 7);      // B row offset
    int bk16 = ((lane >> 3) & 1) * 16;                     // B k-half offset

    float acc[2][8][4];
    #pragma unroll
    for (int i = 0; i < 2; i++)
        #pragma unroll
        for (int j = 0; j < 8; j++)
            #pragma unroll
            for (int c = 0; c < 4; c++) acc[i][j][c] = 0.0f;

    auto load_stage = [&](int s, int t) {
        int k0 = t * 32;
        uint32_t sa = smb + s * STAGE_BYTES;
        uint32_t sbb = sa + OPB;
        #pragma unroll
        for (int i = 0; i < 2; i++) {
            int e = tid + i * 256;
            int row = e >> 2, ch = e & 3;
            cpa16(sa + row * 80 + ch * 16,
                  A + (size_t)(bm + row) * K_ + k0 + ch * 8);
            cpa16(sbb + row * 80 + ch * 16,
                  Bw + (size_t)(bn + row) * K_ + k0 + ch * 8);
        }
    };

    load_stage(0, 0); asm volatile("cp.async.commit_group;");
    if (nt > 1) load_stage(1, 1); asm volatile("cp.async.commit_group;");
    if (nt > 2) load_stage(2, 2); asm volatile("cp.async.commit_group;");

    for (int t = 0; t < nt; t++) {
        if (t + 3 < nt) load_stage((t + 3) & 3, t + 3);
        asm volatile("cp.async.commit_group;");
        asm volatile("cp.async.wait_group 3;");
        __syncthreads();

        uint32_t sA = smb + (t & 3) * STAGE_BYTES;
        uint32_t sB = sA + OPB;
        #pragma unroll
        for (int ks = 0; ks < 2; ks++) {
            uint32_t af[2][4], bf[8][2];
            ldm4(af[0], sA + (wm*32      + l15) * 80 + ks*32 + lk16);
            ldm4(af[1], sA + (wm*32 + 16 + l15) * 80 + ks*32 + lk16);
            #pragma unroll
            for (int np = 0; np < 4; np++) {
                uint32_t d[4];
                ldm4(d, sB + (wn*64 + np*16 + browoff) * 80 + ks*32 + bk16);
                bf[2*np][0] = d[0]; bf[2*np][1] = d[1];
                bf[2*np+1][0] = d[2]; bf[2*np+1][1] = d[3];
            }
            #pragma unroll
            for (int mt = 0; mt < 2; mt++)
                #pragma unroll
                for (int ntile = 0; ntile < 8; ntile++)
                    mma_f16(acc[mt][ntile], af[mt], bf[ntile]);
        }
        __syncthreads();
    }

    #pragma unroll
    for (int mt = 0; mt < 2; mt++) {
        int rr0 = bm + wm * 32 + mt * 16 + g;
        #pragma unroll
        for (int ntile = 0; ntile < 8; ntile++) {
            int cc = bn + wn * 64 + ntile * 8 + 2 * tg;
            #pragma unroll
            for (int half_ = 0; half_ < 2; half_++) {
                int rr = rr0 + half_ * 8;
                float v0 = acc[mt][ntile][half_ * 2 + 0];
                float v1 = acc[mt][ntile][half_ * 2 + 1];
                size_t idx = (size_t)rr * N_ + cc;
                if (EPI == 0) {
                    *(__half2*)((__half*)Cv + idx) = __floats2half2_rn(v0, v1);
                } else {
                    float2 e = *(const float2*)&extra[idx];
                    *(float2*)((float*)Cv + idx) = make_float2(e.x + v0, e.y + v1);
                }
            }
        }
    }
}

// ---------------- fused SwiGLU FFN-in: f3 = silu(A@w1T^T)*(A@w3T^T) ----------
// BM=128, BN=64 per matrix (two B matrices). Same smem/mma budget as gemm_mma.
__global__ __launch_bounds__(256) void gemm_ffn(
    const __half* __restrict__ A, const __half* __restrict__ B1,
    const __half* __restrict__ B3, __half* __restrict__ F3, int K_)
{
    extern __shared__ char smc[];
    uint32_t smb = s2u(smc);
    int tid = threadIdx.x, lane = tid & 31, wid = tid >> 5;
    int wm = wid & 3, wn = wid >> 2;
    int g = lane >> 2, tg = lane & 3;
    int bm = blockIdx.y * 128, bn = blockIdx.x * 64;
    int nt = K_ >> 5;

    int l15 = lane & 15, lk16 = (lane >> 4) * 16;
    int browoff = ((lane >> 4) & 1) * 8 + (lane & 7);
    int bk16 = ((lane >> 3) & 1) * 16;

    float acc[2][2][4][4];
    #pragma unroll
    for (int i = 0; i < 2; i++)
        #pragma unroll
        for (int m = 0; m < 2; m++)
            #pragma unroll
            for (int j = 0; j < 4; j++)
                #pragma unroll
                for (int c = 0; c < 4; c++) acc[i][m][j][c] = 0.0f;

    auto load_stage = [&](int s, int t) {
        int k0 = t * 32;
        uint32_t sa = smb + s * STAGE_BYTES;
        uint32_t sbb = sa + OPB;
        #pragma unroll
        for (int i = 0; i < 2; i++) {
            int e = tid + i * 256;
            int row = e >> 2, ch = e & 3;
            cpa16(sa + row * 80 + ch * 16,
                  A + (size_t)(bm + row) * K_ + k0 + ch * 8);
            const __half* bs = (row < 64)
                ? B1 + (size_t)(bn + row) * K_ + k0 + ch * 8
                : B3 + (size_t)(bn + row - 64) * K_ + k0 + ch * 8;
            cpa16(sbb + row * 80 + ch * 16, bs);
        }
    };

    load_stage(0, 0); asm volatile("cp.async.commit_group;");
    load_stage(1, 1); asm volatile("cp.async.commit_group;");
    load_stage(2, 2); asm volatile("cp.async.commit_group;");

    for (int t = 0; t < nt; t++) {
        if (t + 3 < nt) load_stage((t + 3) & 3, t + 3);
        asm volatile("cp.async.commit_group;");
        asm volatile("cp.async.wait_group 3;");
        __syncthreads();

        uint32_t sA = smb + (t & 3) * STAGE_BYTES;
        uint32_t sB = sA + OPB;
        #pragma unroll
        for (int ks = 0; ks < 2; ks++) {
            uint32_t af[2][4], bf[2][4][2];
            ldm4(af[0], sA + (wm*32      + l15) * 80 + ks*32 + lk16);
            ldm4(af[1], sA + (wm*32 + 16 + l15) * 80 + ks*32 + lk16);
            #pragma unroll
            for (int m = 0; m < 2; m++)
                #pragma unroll
                for (int np = 0; np < 2; np++) {
                    uint32_t d[4];
                    ldm4(d, sB + (m*64 + wn*32 + np*16 + browoff) * 80 + ks*32 + bk16);
                    bf[m][2*np][0] = d[0]; bf[m][2*np][1] = d[1];
                    bf[m][2*np+1][0] = d[2]; bf[m][2*np+1][1] = d[3];
                }
            #pragma unroll
            for (int mt = 0; mt < 2; mt++)
                #pragma unroll
                for (int m = 0; m < 2; m++)
                    #pragma unroll
                    for (int ntile = 0; ntile < 4; ntile++)
                        mma_f16(acc[mt][m][ntile], af[mt], bf[m][ntile]);
        }
        __syncthreads();
    }

    #pragma unroll
    for (int mt = 0; mt < 2; mt++) {
        int rr0 = bm + wm * 32 + mt * 16 + g;
        #pragma unroll
        for (int ntile = 0; ntile < 4; ntile++) {
            int cc = bn + wn * 32 + ntile * 8 + 2 * tg;
            #pragma unroll
            for (int half_ = 0; half_ < 2; half_++) {
                int rr = rr0 + half_ * 8;
                float x10 = acc[mt][0][ntile][half_ * 2 + 0];
                float x11 = acc[mt][0][ntile][half_ * 2 + 1];
                float x30 = acc[mt][1][ntile][half_ * 2 + 0];
                float x31 = acc[mt][1][ntile][half_ * 2 + 1];
                float f0 = x10 / (1.0f + __expf(-x10)) * x30;
                float f1 = x11 / (1.0f + __expf(-x11)) * x31;
                *(__half2*)&F3[(size_t)rr * DFF + cc] = __floats2half2_rn(f0, f1);
            }
        }
    }
}

// ---------------- fp16 MMA flash attention (causal) -------------------------
// grid (S/64, NH, BB), 128 threads = 4 warps; warp w owns rows w*16..w*16+15.
// K/V double-buffered via cp.async; V used via ldmatrix.trans; P stays in regs.
#define ASTR 72                      // halves; row stride 144 bytes
__global__ __launch_bounds__(128) void attn_mma(const __half* __restrict__ qkv,
                                                __half* __restrict__ o) {
    __shared__ __align__(16) __half Qs[64*ASTR];
    __shared__ __align__(16) __half Ks[2][64*ASTR];
    __shared__ __align__(16) __half Vs[2][64*ASTR];

    int qt = blockIdx.x, h = blockIdx.y, b = blockIdx.z;
    int tid = threadIdx.x, lane = tid & 31, wid = tid >> 5;
    int g = lane >> 2, tg = lane & 3;
    const float scale = 0.125f;

    const __half* qb = qkv + (size_t)b * SS * QKVS + h * DH;
    const __half* kb = qb + DM;
    const __half* vb = qb + 2 * DM;

    uint32_t sQ = s2u(Qs);
    uint32_t ksb[2] = { s2u(Ks[0]), s2u(Ks[1]) };
    uint32_t vsb[2] = { s2u(Vs[0]), s2u(Vs[1]) };

    // load Q tile (64 x 64 halves)
    #pragma unroll
    for (int i = 0; i < 4; i++) {
        int e = tid + i * 128;
        int r = e >> 3, c8 = (e & 7) * 8;
        *(uint4*)&Qs[r * ASTR + c8] =
            *(const uint4*)&qb[(size_t)(qt * 64 + r) * QKVS + c8];
    }

    auto issueKV = [&](int kt) {
        int bf_ = kt & 1;
        #pragma unroll
        for (int i = 0; i < 4; i++) {
            int e = tid + i * 128;
            int r = e >> 3, c8 = (e & 7) * 8;
            size_t gidx = (size_t)(kt * 64 + r) * QKVS + c8;
            cpa16(ksb[bf_] + r * 144 + c8 * 2, kb + gidx);
            cpa16(vsb[bf_] + r * 144 + c8 * 2, vb + gidx);
        }
    };
    issueKV(0);
    asm volatile("cp.async.commit_group;");

    float oacc[8][4];
    #pragma unroll
    for (int i = 0; i < 8; i++)
        #pragma unroll
        for (int c = 0; c < 4; c++) oacc[i][c] = 0.0f;
    float mrow[2] = {-1e30f, -1e30f};
    float lrow[2] = {0.0f, 0.0f};

    int rb = wid * 16;
    int l15 = lane & 15, lk16 = (lane >> 4) * 16;
    int browoff = ((lane >> 4) & 1) * 8 + (lane & 7);
    int bk16 = ((lane >> 3) & 1) * 16;
    int vrowoff = ((lane >> 3) & 1) * 8 + (lane & 7);
    int vcol16 = (lane >> 4) * 16;      // bytes: (lane>>4)*8 halves

    for (int kt = 0; kt <= qt; kt++) {
        if (kt < qt) issueKV(kt + 1);
        asm volatile("cp.async.commit_group;");
        asm volatile("cp.async.wait_group 1;");
        __syncthreads();

        uint32_t sK = ksb[kt & 1], sV = vsb[kt & 1];

        // S = Q K^T
        float sacc[8][4];
        #pragma unroll
        for (int i = 0; i < 8; i++)
            #pragma unroll
            for (int c = 0; c < 4; c++) sacc[i][c] = 0.0f;
        #pragma unroll
        for (int kk = 0; kk < 4; kk++) {
            uint32_t af[4];
            ldm4(af, sQ + (rb + l15) * 144 + kk * 32 + lk16);
            #pragma unroll
            for (int np = 0; np < 4; np++) {
                uint32_t d[4];
                ldm4(d, sK + (np * 16 + browoff) * 144 + kk * 32 + bk16);
                uint32_t b0[2] = { d[0], d[1] }, b1[2] = { d[2], d[3] };
                mma_f16(sacc[2*np],   af, b0);
                mma_f16(sacc[2*np+1], af, b1);
            }
        }

        // scale + causal mask
        int row0 = qt * 64 + rb + g, row1 = row0 + 8;
        #pragma unroll
        for (int nt = 0; nt < 8; nt++) {
            int c0 = kt * 64 + nt * 8 + 2 * tg, c1 = c0 + 1;
            sacc[nt][0] *= scale; sacc[nt][1] *= scale;
            sacc[nt][2] *= scale; sacc[nt][3] *= scale;
            if (kt == qt) {
                if (c0 > row0) sacc[nt][0] = -1e30f;
                if (c1 > row0) sacc[nt][1] = -1e30f;
                if (c0 > row1) sacc[nt][2] = -1e30f;
                if (c1 > row1) sacc[nt][3] = -1e30f;
            }
        }

        // online softmax (fragment rows g, g+8)
        float rmax0 = -1e30f, rmax1 = -1e30f;
        #pragma unroll
        for (int nt = 0; nt < 8; nt++) {
            rmax0 = fmaxf(rmax0, fmaxf(sacc[nt][0], sacc[nt][1]));
            rmax1 = fmaxf(rmax1, fmaxf(sacc[nt][2], sacc[nt][3]));
        }
        rmax0 = fmaxf(rmax0, __shfl_xor_sync(0xffffffffu, rmax0, 1));
        rmax0 = fmaxf(rmax0, __shfl_xor_sync(0xffffffffu, rmax0, 2));
        rmax1 = fmaxf(rmax1, __shfl_xor_sync(0xffffffffu, rmax1, 1));
        rmax1 = fmaxf(rmax1, __shfl_xor_sync(0xffffffffu, rmax1, 2));

        float m0 = fmaxf(mrow[0], rmax0), m1 = fmaxf(mrow[1], rmax1);
        float r0 = __expf(mrow[0] - m0), r1 = __expf(mrow[1] - m1);
        mrow[0] = m0; mrow[1] = m1;

        uint32_t plo[8], phi[8];
        float sum0 = 0.0f, sum1 = 0.0f;
        #pragma unroll
        for (int nt = 0; nt < 8; nt++) {
            float p0 = __expf(sacc[nt][0] - m0);
            float p1 = __expf(sacc[nt][1] - m0);
            float p2 = __expf(sacc[nt][2] - m1);
            float p3 = __expf(sacc[nt][3] - m1);
            sum0 += p0 + p1; sum1 += p2 + p3;
            plo[nt] = h2u(p0, p1);
            phi[nt] = h2u(p2, p3);
        }
        sum0 += __shfl_xor_sync(0xffffffffu, sum0, 1);
        sum0 += __shfl_xor_sync(0xffffffffu, sum0, 2);
        sum1 += __shfl_xor_sync(0xffffffffu, sum1, 1);
        sum1 += __shfl_xor_sync(0xffffffffu, sum1, 2);
        lrow[0] = lrow[0] * r0 + sum0;
        lrow[1] = lrow[1] * r1 + sum1;

        #pragma unroll
        for (int dt = 0; dt < 8; dt++) {
            oacc[dt][0] *= r0; oacc[dt][1] *= r0;
            oacc[dt][2] *= r1; oacc[dt][3] *= r1;
        }

        // O += P @ V  (P fragment straight from registers; V via ldmatrix.trans)
        #pragma unroll
        for (int kk = 0; kk < 4; kk++) {
            uint32_t af[4] = { plo[2*kk], phi[2*kk], plo[2*kk+1], phi[2*kk+1] };
            #pragma unroll
            for (int dp = 0; dp < 4; dp++) {
                uint32_t d[4];
                ldm4t(d, sV + (kk * 16 + vrowoff) * 144 + dp * 32 + vcol16);
                uint32_t b0[2] = { d[0], d[1] }, b1[2] = { d[2], d[3] };
                mma_f16(oacc[2*dp],   af, b0);
                mma_f16(oacc[2*dp+1], af, b1);
            }
        }
        __syncthreads();
    }

    float inv0 = 1.0f / lrow[0], inv1 = 1.0f / lrow[1];
    size_t orow0 = (size_t)b * SS + qt * 64 + rb + g;
    #pragma unroll
    for (int dt = 0; dt < 8; dt++) {
        int d = h * DH + dt * 8 + 2 * tg;
        *(__half2*)&o[orow0 * DM + d] =
            __floats2half2_rn(oacc[dt][0] * inv0, oacc[dt][1] * inv0);
        *(__half2*)&o[(orow0 + 8) * DM + d] =
            __floats2half2_rn(oacc[dt][2] * inv1, oacc[dt][3] * inv1);
    }
}

// ---------------- launch ------------------------------------------------------
extern "C" void kernel_launch(void* const* d_in, const int* in_sizes, int n_in,
                              void* d_out, int out_size) {
    const float* x   = (const float*)d_in[0];
    const float* g1  = (const float*)d_in[1];
    const float* g2  = (const float*)d_in[2];
    const float* w_q = (const float*)d_in[3];
    const float* w_k = (const float*)d_in[4];
    const float* w_v = (const float*)d_in[5];
    const float* w_o = (const float*)d_in[6];
    const float* w1  = (const float*)d_in[7];
    const float* w2  = (const float*)d_in[8];
    const float* w3  = (const float*)d_in[9];
    float* out = (float*)d_out;

    __half *xn, *qkv, *ap, *hn, *f3, *wqkvT, *woT, *w1T, *w3T, *w2T;
    float *hres;
    cudaGetSymbolAddress((void**)&xn,    g_xn);
    cudaGetSymbolAddress((void**)&qkv,   g_qkv);
    cudaGetSymbolAddress((void**)&ap,    g_attn);
    cudaGetSymbolAddress((void**)&hres,  g_hres);
    cudaGetSymbolAddress((void**)&hn,    g_hn);
    cudaGetSymbolAddress((void**)&f3,    g_f3);
    cudaGetSymbolAddress((void**)&wqkvT, g_wqkvT);
    cudaGetSymbolAddress((void**)&woT,   g_woT);
    cudaGetSymbolAddress((void**)&w1T,   g_w1T);
    cudaGetSymbolAddress((void**)&w3T,   g_w3T);
    cudaGetSymbolAddress((void**)&w2T,   g_w2T);

    cudaFuncSetAttribute(gemm_mma<0>, cudaFuncAttributeMaxDynamicSharedMemorySize, GSMEM);
    cudaFuncSetAttribute(gemm_mma<1>, cudaFuncAttributeMaxDynamicSharedMemorySize, GSMEM);
    cudaFuncSetAttribute(gemm_ffn, cudaFuncAttributeMaxDynamicSharedMemorySize, GSMEM);

    // weight transposes to fp16 [N,K]; q/k/v stacked into one [3*DM, DM]
    dim3 tb(32, 8);
    transpose_k<<<dim3(DM/32,  DM/32),  tb>>>(w_q, wqkvT,           DM,  DM);
    transpose_k<<<dim3(DM/32,  DM/32),  tb>>>(w_k, wqkvT + DM*DM,   DM,  DM);
    transpose_k<<<dim3(DM/32,  DM/32),  tb>>>(w_v, wqkvT + 2*DM*DM, DM,  DM);
    transpose_k<<<dim3(DM/32,  DM/32),  tb>>>(w_o, woT, DM,  DM);
    transpose_k<<<dim3(DFF/32, DM/32),  tb>>>(w1,  w1T, DM,  DFF);
    transpose_k<<<dim3(DFF/32, DM/32),  tb>>>(w3,  w3T, DM,  DFF);
    transpose_k<<<dim3(DM/32,  DFF/32), tb>>>(w2,  w2T, DFF, DM);

    dim3 gQKV(QKVS / 128, MM / 128);               // (24, 32)
    dim3 gD(DM / 128, MM / 128);                   // (8, 32)
    dim3 gFF(DFF / 64, MM / 128);                  // (43, 32)

    // 1. norm1 -> fp16
    rmsnorm_h<<<MM, 256>>>(x, g1, xn);
    // 2. fused qkv projection -> fp16
    gemm_mma<0><<<gQKV, 256, GSMEM>>>(xn, wqkvT, nullptr, qkv, MM, QKVS, DM);
    // 3. causal flash attention -> fp16
    attn_mma<<<dim3(SS / 64, NH, BB), 128>>>(qkv, ap);
    // 4. h_res = x + attn @ w_o  (fp32)
    gemm_mma<1><<<gD, 256, GSMEM>>>(ap, woT, x, hres, MM, DM, DM);
    // 5. norm2 -> fp16
    rmsnorm_h<<<MM, 256>>>(hres, g2, hn);
    // 6+7. fused f3 = silu(hn @ w1) * (hn @ w3) -> fp16
    gemm_ffn<<<gFF, 256, GSMEM>>>(hn, w1T, w3T, f3, DM);
    // 8. out = h_res + f3 @ w2  (fp32)
    gemm_mma<1><<<gD, 256, GSMEM>>>(f3, w2T, hres, out, MM, DM, DFF);
}